// round 1
// baseline (speedup 1.0000x reference)
#include <cuda_runtime.h>
#include <math.h>

// ---------------- problem constants ----------------
#define TT 64
#define BATCH 32
#define PE 128
#define WE 512
#define PH 256
#define WH 1024
#define PV 48
#define WV 32000

// ---------------- scratch (single __device__ global, no allocs) ----------------
// sizes in floats
#define SZ_PEMB   (TT*BATCH*PE)      // 262144
#define SZ_WEMB   (TT*BATCH*WE)      // 1048576
#define SZ_PH     (BATCH*PH)         // 8192
#define SZ_WH     (BATCH*WH)         // 32768
#define SZ_GP     (BATCH*4*PH)       // 32768
#define SZ_GW     (BATCH*4*WH)       // 131072
#define SZ_PHSEQ  (TT*BATCH*PH)      // 524288
#define SZ_WHSEQ  (TT*BATCH*WH)      // 2097152
#define SZ_HE     (TT*BATCH*WE)      // 1048576

#define OFF_PEMB   0
#define OFF_WEMB   (OFF_PEMB + SZ_PEMB)
#define OFF_PHST   (OFF_WEMB + SZ_WEMB)
#define OFF_PCST   (OFF_PHST + SZ_PH)
#define OFF_WH0    (OFF_PCST + SZ_PH)
#define OFF_WC0    (OFF_WH0 + SZ_WH)
#define OFF_WH1    (OFF_WC0 + SZ_WH)
#define OFF_WC1    (OFF_WH1 + SZ_WH)
#define OFF_LASTW  (OFF_WC1 + SZ_WH)
#define OFF_LASTP  (OFF_LASTW + SZ_WH)
#define OFF_GP     (OFF_LASTP + SZ_PH)
#define OFF_GW     (OFF_GP + SZ_GP)
#define OFF_PHSEQ  (OFF_GW + SZ_GW)
#define OFF_WHSEQ  (OFF_PHSEQ + SZ_PHSEQ)
#define OFF_HE     (OFF_WHSEQ + SZ_WHSEQ)
#define SCRATCH_TOTAL (OFF_HE + SZ_HE)

__device__ float g_scratch[SCRATCH_TOTAL];

// ---------------- init: zero states + gather embeddings ----------------
__global__ void init_kernel(const int* __restrict__ pos, const int* __restrict__ word,
                            const float* __restrict__ pos_emb, const float* __restrict__ word_emb,
                            float* __restrict__ pemb, float* __restrict__ wemb,
                            float* __restrict__ ph, float* __restrict__ pc,
                            float* __restrict__ wh0, float* __restrict__ wc0,
                            float* __restrict__ wh1, float* __restrict__ wc1)
{
    int i = blockIdx.x * blockDim.x + threadIdx.x;
    int stride = gridDim.x * blockDim.x;
    for (int idx = i; idx < TT*BATCH*PE; idx += stride) {
        int tb = idx / PE, e = idx - tb*PE;
        pemb[idx] = pos_emb[pos[tb]*PE + e];
    }
    for (int idx = i; idx < TT*BATCH*WE; idx += stride) {
        int tb = idx / WE, e = idx - tb*WE;
        wemb[idx] = word_emb[word[tb]*WE + e];
    }
    for (int idx = i; idx < BATCH*PH; idx += stride) { ph[idx] = 0.f; pc[idx] = 0.f; }
    for (int idx = i; idx < BATCH*WH; idx += stride) {
        wh0[idx] = 0.f; wc0[idx] = 0.f; wh1[idx] = 0.f; wc1[idx] = 0.f;
    }
}

// ---------------- recurrent small-M GEMM: C[32,N] = sum_i A_i[32,K_i] @ W_i[:,wcol_i:+K_i]^T (+b1+b2) ----------------
struct Pair {
    const float* A; int lda;
    const float* W; int ldw; int wcol;
    int K;
};

__device__ __forceinline__ void rec_accum(const Pair pr, int b, int g, int n0,
                                          float acc[4], float sA[64][33])
{
    for (int kt = 0; kt < pr.K; kt += 64) {
        __syncthreads();
        // stage A tile [32 rows][64 k] transposed into sA[k][b]
        for (int idx = threadIdx.x; idx < 32*64; idx += 256) {
            int bl = idx >> 6, kl = idx & 63;
            sA[kl][bl] = pr.A[bl * pr.lda + kt + kl];
        }
        __syncthreads();
        #pragma unroll 4
        for (int k = 0; k < 64; k += 4) {
            float a0 = sA[k][b], a1 = sA[k+1][b], a2 = sA[k+2][b], a3 = sA[k+3][b];
            #pragma unroll
            for (int j = 0; j < 4; j++) {
                int n = n0 + g + 8*j;
                const float4 wv = *reinterpret_cast<const float4*>(pr.W + n*pr.ldw + pr.wcol + kt + k);
                acc[j] += a0*wv.x + a1*wv.y + a2*wv.z + a3*wv.w;
            }
        }
    }
}

__global__ __launch_bounds__(256) void rec_gemm(Pair p0, Pair p1, Pair p2,
                                                const float* __restrict__ b1,
                                                const float* __restrict__ b2,
                                                float* __restrict__ C, int ldc, int act)
{
    __shared__ float sA[64][33];
    int b = threadIdx.x & 31;
    int g = threadIdx.x >> 5;
    int n0 = blockIdx.x * 32;
    float acc[4] = {0.f, 0.f, 0.f, 0.f};
    if (p0.K) rec_accum(p0, b, g, n0, acc, sA);
    if (p1.K) rec_accum(p1, b, g, n0, acc, sA);
    if (p2.K) rec_accum(p2, b, g, n0, acc, sA);
    #pragma unroll
    for (int j = 0; j < 4; j++) {
        int n = n0 + g + 8*j;
        float v = acc[j];
        if (b1) v += b1[n];
        if (b2) v += b2[n];
        if (act == 1) v = tanhf(v);
        C[b*ldc + n] = v;
    }
}

// ---------------- LSTM cell pointwise ----------------
__global__ void lstm_cell(const float* __restrict__ gates, float* __restrict__ c,
                          float* __restrict__ h, int H, float* __restrict__ hseq)
{
    int i = blockIdx.x * blockDim.x + threadIdx.x;
    if (i >= BATCH * H) return;
    int b = i / H, j = i - b*H;
    const float* gr = gates + b*4*H;
    float ig = gr[j], fg = gr[H + j], gg = gr[2*H + j], og = gr[3*H + j];
    float si = 1.f / (1.f + expf(-ig));
    float sf = 1.f / (1.f + expf(-fg));
    float so = 1.f / (1.f + expf(-og));
    float cn = sf * c[i] + si * tanhf(gg);
    float hn = so * tanhf(cn);
    c[i] = cn; h[i] = hn;
    if (hseq) hseq[i] = hn;
}

// ---------------- big tiled GEMM: C[M,N] = A[M,K] @ W[N,K]^T + bias ----------------
__global__ __launch_bounds__(256) void big_gemm(const float* __restrict__ A, int lda,
                                                const float* __restrict__ W, int ldw,
                                                const float* __restrict__ bias,
                                                float* __restrict__ C, int ldc, int K)
{
    __shared__ float sA[16][66];
    __shared__ float sW[16][66];
    int tx = threadIdx.x & 15, ty = threadIdx.x >> 4;
    int bm = blockIdx.y * 64, bn = blockIdx.x * 64;
    float acc[4][4] = {};
    for (int kt = 0; kt < K; kt += 16) {
        __syncthreads();
        {
            int ml = threadIdx.x >> 2;          // 0..63
            int kq = (threadIdx.x & 3) * 4;     // 0,4,8,12
            float4 av = *reinterpret_cast<const float4*>(A + (bm + ml)*lda + kt + kq);
            sA[kq][ml] = av.x; sA[kq+1][ml] = av.y; sA[kq+2][ml] = av.z; sA[kq+3][ml] = av.w;
            float4 wv = *reinterpret_cast<const float4*>(W + (bn + ml)*ldw + kt + kq);
            sW[kq][ml] = wv.x; sW[kq+1][ml] = wv.y; sW[kq+2][ml] = wv.z; sW[kq+3][ml] = wv.w;
        }
        __syncthreads();
        #pragma unroll
        for (int k = 0; k < 16; k++) {
            float a[4], w[4];
            #pragma unroll
            for (int i = 0; i < 4; i++) a[i] = sA[k][ty*4 + i];
            #pragma unroll
            for (int j = 0; j < 4; j++) w[j] = sW[k][tx*4 + j];
            #pragma unroll
            for (int i = 0; i < 4; i++)
                #pragma unroll
                for (int j = 0; j < 4; j++)
                    acc[i][j] += a[i] * w[j];
        }
    }
    #pragma unroll
    for (int i = 0; i < 4; i++) {
        int m = bm + ty*4 + i;
        long rowoff = (long)m * ldc;
        #pragma unroll
        for (int j = 0; j < 4; j++) {
            int n = bn + tx*4 + j;
            float v = acc[i][j] + (bias ? bias[n] : 0.f);
            C[rowoff + n] = v;
        }
    }
}

// ---------------- pos projection + log_softmax (48-way) ----------------
__global__ void pos_out_kernel(const float* __restrict__ phseq,
                               const float* __restrict__ proj_W,
                               const float* __restrict__ proj_b,
                               float* __restrict__ out)
{
    int row = blockIdx.x;   // T*B rows
    const float* h = phseq + row * PH;
    __shared__ float sh[PH];
    __shared__ float logits[PV];
    __shared__ float lse;
    for (int i = threadIdx.x; i < PH; i += 64) sh[i] = h[i];
    __syncthreads();
    if (threadIdx.x < PV) {
        float s = proj_b[threadIdx.x];
        const float* wr = proj_W + threadIdx.x * PH;
        #pragma unroll 4
        for (int k = 0; k < PH; k++) s += sh[k] * wr[k];
        logits[threadIdx.x] = s;
    }
    __syncthreads();
    if (threadIdx.x == 0) {
        float m = -1e30f;
        for (int i = 0; i < PV; i++) m = fmaxf(m, logits[i]);
        float s = 0.f;
        for (int i = 0; i < PV; i++) s += expf(logits[i] - m);
        lse = m + logf(s);
    }
    __syncthreads();
    if (threadIdx.x < PV) out[row * PV + threadIdx.x] = logits[threadIdx.x] - lse;
}

// ---------------- in-place log_softmax over rows of WV ----------------
__global__ void word_lsm(float* __restrict__ out)
{
    int row = blockIdx.x;
    float* r = out + (long)row * WV;
    float m = -1e30f, s = 0.f;
    for (int i = threadIdx.x; i < WV; i += blockDim.x) {
        float v = r[i];
        if (v > m) { s = s * expf(m - v) + 1.f; m = v; }
        else       { s += expf(v - m); }
    }
    __shared__ float sm[256], ss[256];
    sm[threadIdx.x] = m; ss[threadIdx.x] = s;
    __syncthreads();
    for (int off = 128; off > 0; off >>= 1) {
        if (threadIdx.x < off) {
            float m1 = sm[threadIdx.x], s1 = ss[threadIdx.x];
            float m2 = sm[threadIdx.x + off], s2 = ss[threadIdx.x + off];
            float mm = fmaxf(m1, m2);
            sm[threadIdx.x] = mm;
            ss[threadIdx.x] = s1 * expf(m1 - mm) + s2 * expf(m2 - mm);
        }
        __syncthreads();
    }
    float lse = sm[0] + logf(ss[0]);
    for (int i = threadIdx.x; i < WV; i += blockDim.x) r[i] -= lse;
}

// ---------------- host orchestration ----------------
static inline Pair mkp(const float* A, int lda, const float* W, int ldw, int wcol, int K) {
    Pair p; p.A = A; p.lda = lda; p.W = W; p.ldw = ldw; p.wcol = wcol; p.K = K; return p;
}

extern "C" void kernel_launch(void* const* d_in, const int* in_sizes, int n_in,
                              void* d_out, int out_size)
{
    (void)in_sizes; (void)n_in; (void)out_size;
    const int*   pos          = (const int*)  d_in[0];
    const int*   word         = (const int*)  d_in[1];
    const float* pos_emb_W    = (const float*)d_in[2];
    const float* word_emb_W   = (const float*)d_in[3];
    const float* w2p_W        = (const float*)d_in[4];
    const float* w2p_b        = (const float*)d_in[5];
    const float* p2w_W        = (const float*)d_in[6];
    const float* p2w_b        = (const float*)d_in[7];
    const float* p_Wih0       = (const float*)d_in[8];
    const float* p_Whh0       = (const float*)d_in[9];
    const float* p_bih0       = (const float*)d_in[10];
    const float* p_bhh0       = (const float*)d_in[11];
    const float* w_Wih0       = (const float*)d_in[12];
    const float* w_Whh0       = (const float*)d_in[13];
    const float* w_bih0       = (const float*)d_in[14];
    const float* w_bhh0       = (const float*)d_in[15];
    const float* w_Wih1       = (const float*)d_in[16];
    const float* w_Whh1       = (const float*)d_in[17];
    const float* w_bih1       = (const float*)d_in[18];
    const float* w_bhh1       = (const float*)d_in[19];
    const float* pos_proj_W   = (const float*)d_in[20];
    const float* pos_proj_b   = (const float*)d_in[21];
    const float* word_proj1_W = (const float*)d_in[22];
    const float* word_proj1_b = (const float*)d_in[23];
    const float* word_proj2_b = (const float*)d_in[24];
    float* out = (float*)d_out;

    float* S = nullptr;
    cudaGetSymbolAddress((void**)&S, g_scratch);
    float* pemb   = S + OFF_PEMB;
    float* wemb   = S + OFF_WEMB;
    float* ph     = S + OFF_PHST;
    float* pc     = S + OFF_PCST;
    float* wh0    = S + OFF_WH0;
    float* wc0    = S + OFF_WC0;
    float* wh1    = S + OFF_WH1;
    float* wc1    = S + OFF_WC1;
    float* lastw  = S + OFF_LASTW;
    float* lastp  = S + OFF_LASTP;
    float* gp     = S + OFF_GP;
    float* gw     = S + OFF_GW;
    float* phseq  = S + OFF_PHSEQ;
    float* whseq  = S + OFF_WHSEQ;
    float* he     = S + OFF_HE;

    Pair z = mkp(nullptr, 0, nullptr, 0, 0, 0);

    init_kernel<<<256, 256>>>(pos, word, pos_emb_W, word_emb_W,
                              pemb, wemb, ph, pc, wh0, wc0, wh1, wc1);

    for (int t = 0; t < TT; t++) {
        // last_w = tanh(wh1 @ w2p_W^T + b)
        rec_gemm<<<WH/32, 256>>>(mkp(wh1, WH, w2p_W, WH, 0, WH), z, z,
                                 w2p_b, nullptr, lastw, WH, 1);
        // POS gates = [pemb_t | last_w] @ p_Wih0^T + ph @ p_Whh0^T + b
        rec_gemm<<<(4*PH)/32, 256>>>(mkp(pemb + t*BATCH*PE, PE, p_Wih0, PE + WH, 0, PE),
                                     mkp(lastw, WH, p_Wih0, PE + WH, PE, WH),
                                     mkp(ph, PH, p_Whh0, PH, 0, PH),
                                     p_bih0, p_bhh0, gp, 4*PH, 0);
        lstm_cell<<<(BATCH*PH + 255)/256, 256>>>(gp, pc, ph, PH, phseq + t*BATCH*PH);
        // last_p = tanh(ph_new @ p2w_W^T + b)
        rec_gemm<<<PH/32, 256>>>(mkp(ph, PH, p2w_W, PH, 0, PH), z, z,
                                 p2w_b, nullptr, lastp, PH, 1);
        // word L0 gates = [wemb_t | last_p] @ w_Wih0^T + wh0 @ w_Whh0^T + b
        rec_gemm<<<(4*WH)/32, 256>>>(mkp(wemb + t*BATCH*WE, WE, w_Wih0, WE + PH, 0, WE),
                                     mkp(lastp, PH, w_Wih0, WE + PH, WE, PH),
                                     mkp(wh0, WH, w_Whh0, WH, 0, WH),
                                     w_bih0, w_bhh0, gw, 4*WH, 0);
        lstm_cell<<<(BATCH*WH + 255)/256, 256>>>(gw, wc0, wh0, WH, nullptr);
        // word L1 gates = wh0_new @ w_Wih1^T + wh1 @ w_Whh1^T + b
        rec_gemm<<<(4*WH)/32, 256>>>(mkp(wh0, WH, w_Wih1, WH, 0, WH),
                                     mkp(wh1, WH, w_Whh1, WH, 0, WH), z,
                                     w_bih1, w_bhh1, gw, 4*WH, 0);
        lstm_cell<<<(BATCH*WH + 255)/256, 256>>>(gw, wc1, wh1, WH, whseq + t*BATCH*WH);
    }

    // Phase B: outputs (fully parallel over T*B rows)
    pos_out_kernel<<<TT*BATCH, 64>>>(phseq, pos_proj_W, pos_proj_b, out);

    // he[2048,512] = whseq[2048,1024] @ word_proj1_W[512,1024]^T + b
    big_gemm<<<dim3(WE/64, (TT*BATCH)/64), 256>>>(whseq, WH, word_proj1_W, WH,
                                                  word_proj1_b, he, WE, WH);
    // logits[2048,32000] = he @ word_emb_W[32000,512]^T + b2  (into d_out word region)
    float* wout = out + TT*BATCH*PV;
    big_gemm<<<dim3(WV/64, (TT*BATCH)/64), 256>>>(he, WE, word_emb_W, WE,
                                                  word_proj2_b, wout, WV, WE);
    word_lsm<<<TT*BATCH, 256>>>(wout);
}

// round 2
// speedup vs baseline: 1.3468x; 1.3468x over previous
#include <cuda_runtime.h>
#include <math.h>

// ---------------- problem constants ----------------
#define TT 64
#define BATCH 32
#define PE 128
#define WE 512
#define PH 256
#define WH 1024
#define PV 48
#define WV 32000

// ---------------- scratch ----------------
#define SZ_PEMB   (TT*BATCH*PE)
#define SZ_WEMB   (TT*BATCH*WE)
#define SZ_GPSEQ  (TT*BATCH*4*PH)
#define SZ_GWSEQ  (TT*BATCH*4*WH)
#define SZ_PH     (BATCH*PH)
#define SZ_WH     (BATCH*WH)
#define SZ_PHSEQ  (TT*BATCH*PH)
#define SZ_WHSEQ  (TT*BATCH*WH)
#define SZ_HE     (TT*BATCH*WE)

#define OFF_PEMB   0
#define OFF_WEMB   (OFF_PEMB + SZ_PEMB)
#define OFF_GPSEQ  (OFF_WEMB + SZ_WEMB)
#define OFF_GWSEQ  (OFF_GPSEQ + SZ_GPSEQ)
#define OFF_PH0    (OFF_GWSEQ + SZ_GWSEQ)
#define OFF_PH1    (OFF_PH0 + SZ_PH)
#define OFF_PC     (OFF_PH1 + SZ_PH)
#define OFF_WH0A   (OFF_PC + SZ_PH)
#define OFF_WH0B   (OFF_WH0A + SZ_WH)
#define OFF_WC0    (OFF_WH0B + SZ_WH)
#define OFF_WH1A   (OFF_WC0 + SZ_WH)
#define OFF_WH1B   (OFF_WH1A + SZ_WH)
#define OFF_WC1    (OFF_WH1B + SZ_WH)
#define OFF_LASTW  (OFF_WC1 + SZ_WH)
#define OFF_LASTP  (OFF_LASTW + SZ_WH)
#define OFF_PHSEQ  (OFF_LASTP + SZ_PH)
#define OFF_WHSEQ  (OFF_PHSEQ + SZ_PHSEQ)
#define OFF_HE     (OFF_WHSEQ + SZ_WHSEQ)
#define SCRATCH_TOTAL (OFF_HE + SZ_HE)

__device__ float g_scratch[SCRATCH_TOTAL];

// ---------------- init: zero states + gather embeddings ----------------
__global__ void init_kernel(const int* __restrict__ pos, const int* __restrict__ word,
                            const float* __restrict__ pos_emb, const float* __restrict__ word_emb,
                            float* __restrict__ S)
{
    int i = blockIdx.x * blockDim.x + threadIdx.x;
    int stride = gridDim.x * blockDim.x;
    float* pemb = S + OFF_PEMB;
    float* wemb = S + OFF_WEMB;
    for (int idx = i; idx < TT*BATCH*PE; idx += stride) {
        int tb = idx / PE, e = idx - tb*PE;
        pemb[idx] = pos_emb[pos[tb]*PE + e];
    }
    for (int idx = i; idx < TT*BATCH*WE; idx += stride) {
        int tb = idx / WE, e = idx - tb*WE;
        wemb[idx] = word_emb[word[tb]*WE + e];
    }
    // zero states (both ping-pong h buffers + c states)
    for (int idx = i; idx < 2*SZ_PH + SZ_PH; idx += stride) S[OFF_PH0 + idx] = 0.f;
    for (int idx = i; idx < 6*SZ_WH; idx += stride) S[OFF_WH0A + idx] = 0.f;
}

// ---------------- pair descriptor for recurrent GEMMs ----------------
struct Pair {
    const float* A;   // [32, K] row-major, lda == K
    const float* W;   // rows of length ldw, dot over cols [wcol, wcol+K)
    int ldw, wcol, K;
};

__device__ __forceinline__ void stage_A(const float* __restrict__ A, int K, int kt,
                                        float sA[64][33])
{
    #pragma unroll
    for (int idx = threadIdx.x; idx < 32*64; idx += 256) {
        int bl = idx >> 6, kl = idx & 63;
        sA[kl][bl] = A[bl*K + kt + kl];
    }
}

template<int NC>
__device__ __forceinline__ void accum_pair(Pair p, int b, const int* __restrict__ n,
                                           float* __restrict__ acc, float sA[64][33])
{
    const float* Wr[NC];
    #pragma unroll
    for (int c = 0; c < NC; c++) Wr[c] = p.W + (long)n[c]*p.ldw + p.wcol;
    for (int kt = 0; kt < p.K; kt += 64) {
        __syncthreads();
        stage_A(p.A, p.K, kt, sA);
        __syncthreads();
        #pragma unroll 8
        for (int k = 0; k < 64; k += 4) {
            float a0 = sA[k][b], a1 = sA[k+1][b], a2 = sA[k+2][b], a3 = sA[k+3][b];
            #pragma unroll
            for (int c = 0; c < NC; c++) {
                const float4 w = *reinterpret_cast<const float4*>(Wr[c] + kt + k);
                acc[c] = fmaf(a0, w.x, fmaf(a1, w.y, fmaf(a2, w.z, fmaf(a3, w.w, acc[c]))));
            }
        }
    }
}

__device__ __forceinline__ float sigf(float x) { return 1.f / (1.f + expf(-x)); }

// ---------------- fused gates GEMM + LSTM cell ----------------
// Block covers J hidden units x 4 gates (4J weight rows). 256 threads.
template<int H, int J>
__global__ __launch_bounds__(256) void gate_cell(
    Pair p0, Pair p1,
    const float* __restrict__ pre,   // [32, 4H] per-t precomputed input-part (incl. biases), or null
    const float* __restrict__ b1, const float* __restrict__ b2,  // used when pre==null
    float* __restrict__ c_st, float* __restrict__ h_out, float* __restrict__ hseq)
{
    constexpr int NC = J / 2;         // columns per thread (8 warps cover 4J cols)
    __shared__ float sA[64][33];
    __shared__ float sacc[32][4*J + 1];
    int b = threadIdx.x & 31;
    int q = threadIdx.x >> 5;
    int j0 = blockIdx.x * J;

    int n[NC];
    float acc[NC];
    #pragma unroll
    for (int c = 0; c < NC; c++) {
        int cc = q*NC + c;
        int gate = cc / J, jj = cc % J;
        n[c] = gate*H + j0 + jj;
        acc[c] = 0.f;
    }

    accum_pair<NC>(p0, b, n, acc, sA);
    accum_pair<NC>(p1, b, n, acc, sA);

    #pragma unroll
    for (int c = 0; c < NC; c++) sacc[b][q*NC + c] = acc[c];
    __syncthreads();

    if (threadIdx.x < 32*J) {
        int be = threadIdx.x & 31;
        int jj = threadIdx.x >> 5;        // 0..J-1
        int j  = j0 + jj;
        float gi = sacc[be][0*J + jj];
        float gf = sacc[be][1*J + jj];
        float gg = sacc[be][2*J + jj];
        float go = sacc[be][3*J + jj];
        if (pre) {
            const float* pr = pre + be*4*H;
            gi += pr[0*H + j]; gf += pr[1*H + j];
            gg += pr[2*H + j]; go += pr[3*H + j];
        } else {
            gi += b1[0*H + j] + b2[0*H + j];
            gf += b1[1*H + j] + b2[1*H + j];
            gg += b1[2*H + j] + b2[2*H + j];
            go += b1[3*H + j] + b2[3*H + j];
        }
        float si = sigf(gi), sf = sigf(gf), so = sigf(go);
        int idx = be*H + j;
        float cn = sf * c_st[idx] + si * tanhf(gg);
        float hn = so * tanhf(cn);
        c_st[idx] = cn;
        h_out[idx] = hn;
        if (hseq) hseq[idx] = hn;
    }
}

// ---------------- small tanh GEMM: out[32,N] = tanh(A[32,K] @ W[N,K]^T + b) ----------------
__global__ __launch_bounds__(256) void tanh_gemm(const float* __restrict__ A,
                                                 const float* __restrict__ W, int K,
                                                 const float* __restrict__ bias,
                                                 float* __restrict__ out, int N)
{
    __shared__ float sA[64][33];
    int b = threadIdx.x & 31;
    int q = threadIdx.x >> 5;
    int n[2];
    n[0] = blockIdx.x*16 + q*2;
    n[1] = n[0] + 1;
    float acc[2] = {0.f, 0.f};
    Pair p; p.A = A; p.W = W; p.ldw = K; p.wcol = 0; p.K = K;
    accum_pair<2>(p, b, n, acc, sA);
    #pragma unroll
    for (int c = 0; c < 2; c++)
        out[b*N + n[c]] = tanhf(acc[c] + bias[n[c]]);
}

// ---------------- big GEMM: C[M,N] = A[M,K] @ W[N, wcol:wcol+K]^T + b1 (+b2) ----------------
// BM=128, BN=64, BK=16, 256 threads, 8x4 per thread.
__global__ __launch_bounds__(256) void big_gemm(const float* __restrict__ A, int lda,
                                                const float* __restrict__ W, int ldw, int wcol,
                                                const float* __restrict__ bias1,
                                                const float* __restrict__ bias2,
                                                float* __restrict__ C, long ldc, int K)
{
    __shared__ float sA[16][132];
    __shared__ float sW[16][68];
    int tx = threadIdx.x & 15, ty = threadIdx.x >> 4;
    int bm = blockIdx.y * 128, bn = blockIdx.x * 64;
    float acc[8][4];
    #pragma unroll
    for (int i = 0; i < 8; i++)
        #pragma unroll
        for (int j = 0; j < 4; j++) acc[i][j] = 0.f;

    for (int kt = 0; kt < K; kt += 16) {
        __syncthreads();
        #pragma unroll
        for (int i = 0; i < 2; i++) {
            int f = threadIdx.x + i*256;         // 0..511
            int row = f >> 2, kq = (f & 3) * 4;
            float4 v = *reinterpret_cast<const float4*>(A + (long)(bm+row)*lda + kt + kq);
            sA[kq][row] = v.x; sA[kq+1][row] = v.y; sA[kq+2][row] = v.z; sA[kq+3][row] = v.w;
        }
        {
            int f = threadIdx.x;                  // 0..255
            int row = f >> 2, kq = (f & 3) * 4;
            float4 v = *reinterpret_cast<const float4*>(W + (long)(bn+row)*ldw + wcol + kt + kq);
            sW[kq][row] = v.x; sW[kq+1][row] = v.y; sW[kq+2][row] = v.z; sW[kq+3][row] = v.w;
        }
        __syncthreads();
        #pragma unroll
        for (int k = 0; k < 16; k++) {
            float4 a0 = *reinterpret_cast<float4*>(&sA[k][ty*8]);
            float4 a1 = *reinterpret_cast<float4*>(&sA[k][ty*8+4]);
            float4 w  = *reinterpret_cast<float4*>(&sW[k][tx*4]);
            float am[8] = {a0.x,a0.y,a0.z,a0.w,a1.x,a1.y,a1.z,a1.w};
            float wn[4] = {w.x,w.y,w.z,w.w};
            #pragma unroll
            for (int i = 0; i < 8; i++)
                #pragma unroll
                for (int j = 0; j < 4; j++)
                    acc[i][j] = fmaf(am[i], wn[j], acc[i][j]);
        }
    }

    float bv[4];
    #pragma unroll
    for (int j = 0; j < 4; j++) {
        int nn = bn + tx*4 + j;
        bv[j] = (bias1 ? bias1[nn] : 0.f) + (bias2 ? bias2[nn] : 0.f);
    }
    #pragma unroll
    for (int i = 0; i < 8; i++) {
        int m = bm + ty*8 + i;
        float4 o;
        o.x = acc[i][0] + bv[0]; o.y = acc[i][1] + bv[1];
        o.z = acc[i][2] + bv[2]; o.w = acc[i][3] + bv[3];
        *reinterpret_cast<float4*>(C + (long)m*ldc + bn + tx*4) = o;
    }
}

// ---------------- pos projection + log_softmax (48-way) ----------------
__global__ void pos_out_kernel(const float* __restrict__ phseq,
                               const float* __restrict__ proj_W,
                               const float* __restrict__ proj_b,
                               float* __restrict__ out)
{
    int row = blockIdx.x;   // T*B rows
    const float* h = phseq + row * PH;
    __shared__ float sh[PH];
    __shared__ float logits[PV];
    __shared__ float lse;
    for (int i = threadIdx.x; i < PH; i += 64) sh[i] = h[i];
    __syncthreads();
    if (threadIdx.x < PV) {
        float s = proj_b[threadIdx.x];
        const float* wr = proj_W + threadIdx.x * PH;
        #pragma unroll 4
        for (int k = 0; k < PH; k++) s += sh[k] * wr[k];
        logits[threadIdx.x] = s;
    }
    __syncthreads();
    if (threadIdx.x == 0) {
        float m = -1e30f;
        for (int i = 0; i < PV; i++) m = fmaxf(m, logits[i]);
        float s = 0.f;
        for (int i = 0; i < PV; i++) s += expf(logits[i] - m);
        lse = m + logf(s);
    }
    __syncthreads();
    if (threadIdx.x < PV) out[row * PV + threadIdx.x] = logits[threadIdx.x] - lse;
}

// ---------------- in-place log_softmax over rows of WV ----------------
__global__ void word_lsm(float* __restrict__ out)
{
    int row = blockIdx.x;
    float* r = out + (long)row * WV;
    float m = -1e30f, s = 0.f;
    for (int i = threadIdx.x; i < WV; i += blockDim.x) {
        float v = r[i];
        if (v > m) { s = s * expf(m - v) + 1.f; m = v; }
        else       { s += expf(v - m); }
    }
    __shared__ float sm[256], ss[256];
    sm[threadIdx.x] = m; ss[threadIdx.x] = s;
    __syncthreads();
    for (int off = 128; off > 0; off >>= 1) {
        if (threadIdx.x < off) {
            float m1 = sm[threadIdx.x], s1 = ss[threadIdx.x];
            float m2 = sm[threadIdx.x + off], s2 = ss[threadIdx.x + off];
            float mm = fmaxf(m1, m2);
            sm[threadIdx.x] = mm;
            ss[threadIdx.x] = s1 * expf(m1 - mm) + s2 * expf(m2 - mm);
        }
        __syncthreads();
    }
    float lse = sm[0] + logf(ss[0]);
    for (int i = threadIdx.x; i < WV; i += blockDim.x) r[i] -= lse;
}

// ---------------- host orchestration ----------------
static inline Pair mkp(const float* A, const float* W, int ldw, int wcol, int K) {
    Pair p; p.A = A; p.W = W; p.ldw = ldw; p.wcol = wcol; p.K = K; return p;
}

extern "C" void kernel_launch(void* const* d_in, const int* in_sizes, int n_in,
                              void* d_out, int out_size)
{
    (void)in_sizes; (void)n_in; (void)out_size;
    const int*   pos          = (const int*)  d_in[0];
    const int*   word         = (const int*)  d_in[1];
    const float* pos_emb_W    = (const float*)d_in[2];
    const float* word_emb_W   = (const float*)d_in[3];
    const float* w2p_W        = (const float*)d_in[4];
    const float* w2p_b        = (const float*)d_in[5];
    const float* p2w_W        = (const float*)d_in[6];
    const float* p2w_b        = (const float*)d_in[7];
    const float* p_Wih0       = (const float*)d_in[8];
    const float* p_Whh0       = (const float*)d_in[9];
    const float* p_bih0       = (const float*)d_in[10];
    const float* p_bhh0       = (const float*)d_in[11];
    const float* w_Wih0       = (const float*)d_in[12];
    const float* w_Whh0       = (const float*)d_in[13];
    const float* w_bih0       = (const float*)d_in[14];
    const float* w_bhh0       = (const float*)d_in[15];
    const float* w_Wih1       = (const float*)d_in[16];
    const float* w_Whh1       = (const float*)d_in[17];
    const float* w_bih1       = (const float*)d_in[18];
    const float* w_bhh1       = (const float*)d_in[19];
    const float* pos_proj_W   = (const float*)d_in[20];
    const float* pos_proj_b   = (const float*)d_in[21];
    const float* word_proj1_W = (const float*)d_in[22];
    const float* word_proj1_b = (const float*)d_in[23];
    const float* word_proj2_b = (const float*)d_in[24];
    float* out = (float*)d_out;

    float* S = nullptr;
    cudaGetSymbolAddress((void**)&S, g_scratch);
    float* pemb  = S + OFF_PEMB;
    float* wemb  = S + OFF_WEMB;
    float* gpseq = S + OFF_GPSEQ;
    float* gwseq = S + OFF_GWSEQ;
    float* phb[2]  = { S + OFF_PH0,  S + OFF_PH1 };
    float* pc    = S + OFF_PC;
    float* wh0b[2] = { S + OFF_WH0A, S + OFF_WH0B };
    float* wc0   = S + OFF_WC0;
    float* wh1b[2] = { S + OFF_WH1A, S + OFF_WH1B };
    float* wc1   = S + OFF_WC1;
    float* lastw = S + OFF_LASTW;
    float* lastp = S + OFF_LASTP;
    float* phseq = S + OFF_PHSEQ;
    float* whseq = S + OFF_WHSEQ;
    float* he    = S + OFF_HE;

    init_kernel<<<256, 256>>>(pos, word, pos_emb_W, word_emb_W, S);

    // Precompute input-side gate contributions for all t (parallel):
    // gpseq[tb, :] = pemb[tb,:] @ p_Wih0[:, :PE]^T + p_bih0 + p_bhh0
    big_gemm<<<dim3(4*PH/64, TT*BATCH/128), 256>>>(pemb, PE, p_Wih0, PE+WH, 0,
                                                   p_bih0, p_bhh0, gpseq, 4*PH, PE);
    // gwseq[tb, :] = wemb[tb,:] @ w_Wih0[:, :WE]^T + w_bih0 + w_bhh0
    big_gemm<<<dim3(4*WH/64, TT*BATCH/128), 256>>>(wemb, WE, w_Wih0, WE+PH, 0,
                                                   w_bih0, w_bhh0, gwseq, 4*WH, WE);

    int pp = 0, pw0 = 0, pw1 = 0;   // ping-pong indices (current = stable)
    for (int t = 0; t < TT; t++) {
        // last_w = tanh(wh1 @ w2p_W^T + b)
        tanh_gemm<<<WH/16, 256>>>(wh1b[pw1], w2p_W, WH, w2p_b, lastw, WH);
        // POS gates + cell
        gate_cell<PH, 4><<<PH/4, 256>>>(
            mkp(lastw, p_Wih0, PE+WH, PE, WH),
            mkp(phb[pp], p_Whh0, PH, 0, PH),
            gpseq + (long)t*BATCH*4*PH, nullptr, nullptr,
            pc, phb[pp^1], phseq + (long)t*BATCH*PH);
        pp ^= 1;
        // last_p = tanh(ph_new @ p2w_W^T + b)
        tanh_gemm<<<PH/16, 256>>>(phb[pp], p2w_W, PH, p2w_b, lastp, PH);
        // WORD layer0 gates + cell
        gate_cell<WH, 8><<<WH/8, 256>>>(
            mkp(lastp, w_Wih0, WE+PH, WE, PH),
            mkp(wh0b[pw0], w_Whh0, WH, 0, WH),
            gwseq + (long)t*BATCH*4*WH, nullptr, nullptr,
            wc0, wh0b[pw0^1], nullptr);
        pw0 ^= 1;
        // WORD layer1 gates + cell
        gate_cell<WH, 8><<<WH/8, 256>>>(
            mkp(wh0b[pw0], w_Wih1, WH, 0, WH),
            mkp(wh1b[pw1], w_Whh1, WH, 0, WH),
            nullptr, w_bih1, w_bhh1,
            wc1, wh1b[pw1^1], whseq + (long)t*BATCH*WH);
        pw1 ^= 1;
    }

    // Phase B: outputs (fully parallel over T*B rows)
    pos_out_kernel<<<TT*BATCH, 64>>>(phseq, pos_proj_W, pos_proj_b, out);

    // he[2048,512] = whseq @ word_proj1_W^T + b
    big_gemm<<<dim3(WE/64, TT*BATCH/128), 256>>>(whseq, WH, word_proj1_W, WH, 0,
                                                 word_proj1_b, nullptr, he, WE, WH);
    // logits[2048,32000] = he @ word_emb_W^T + b2
    float* wout = out + (long)TT*BATCH*PV;
    big_gemm<<<dim3(WV/64, TT*BATCH/128), 256>>>(he, WE, word_emb_W, WE, 0,
                                                 word_proj2_b, nullptr, wout, WV, WE);
    word_lsm<<<TT*BATCH, 256>>>(wout);
}

// round 3
// speedup vs baseline: 2.8475x; 2.1143x over previous
#include <cuda_runtime.h>
#include <math.h>

// ---------------- problem constants ----------------
#define TT 64
#define BATCH 32
#define PE 128
#define WE 512
#define PH 256
#define WH 1024
#define PV 48
#define WV 32000

#define GRID 148
#define TPB  512

// ---------------- scratch ----------------
#define SZ_PEMB   (TT*BATCH*PE)
#define SZ_WEMB   (TT*BATCH*WE)
#define SZ_GPSEQ  (TT*BATCH*4*PH)
#define SZ_GWSEQ  (TT*BATCH*4*WH)
#define SZ_PH     (BATCH*PH)
#define SZ_WH     (BATCH*WH)
#define SZ_G4WH   (BATCH*4*WH)
#define SZ_PHSEQ  (TT*BATCH*PH)
#define SZ_WHSEQ  (TT*BATCH*WH)
#define SZ_HE     (TT*BATCH*WE)

#define OFF_PEMB   0
#define OFF_WEMB   (OFF_PEMB + SZ_PEMB)
#define OFF_GPSEQ  (OFF_WEMB + SZ_WEMB)
#define OFF_GWSEQ  (OFF_GPSEQ + SZ_GPSEQ)
#define OFF_PH0    (OFF_GWSEQ + SZ_GWSEQ)
#define OFF_PH1    (OFF_PH0 + SZ_PH)
#define OFF_PC     (OFF_PH1 + SZ_PH)
#define OFF_WH0A   (OFF_PC + SZ_PH)
#define OFF_WH0B   (OFF_WH0A + SZ_WH)
#define OFF_WC0    (OFF_WH0B + SZ_WH)
#define OFF_WH1A   (OFF_WC0 + SZ_WH)
#define OFF_WH1B   (OFF_WH1A + SZ_WH)
#define OFF_WC1    (OFF_WH1B + SZ_WH)
#define OFF_LASTW  (OFF_WC1 + SZ_WH)
#define OFF_LASTP  (OFF_LASTW + SZ_WH)
#define OFF_WG0H   (OFF_LASTP + SZ_PH)
#define OFF_WG1H   (OFF_WG0H + SZ_G4WH)
#define OFF_PHSEQ  (OFF_WG1H + SZ_G4WH)
#define OFF_WHSEQ  (OFF_PHSEQ + SZ_PHSEQ)
#define OFF_HE     (OFF_WHSEQ + SZ_WHSEQ)
#define SCRATCH_TOTAL (OFF_HE + SZ_HE)

__device__ float g_scratch[SCRATCH_TOTAL];
__device__ unsigned g_bar_cnt = 0;
__device__ unsigned g_bar_gen = 0;

// dynamic smem: 32 rows x (1024/4+1) float4
#define SMEM_DYN (32 * 257 * 16)

__device__ __forceinline__ float sigf(float x) { return 1.f / (1.f + expf(-x)); }

// ---------------- init ----------------
__global__ void init_kernel(const int* __restrict__ pos, const int* __restrict__ word,
                            const float* __restrict__ pos_emb, const float* __restrict__ word_emb,
                            float* __restrict__ S)
{
    int i = blockIdx.x * blockDim.x + threadIdx.x;
    int stride = gridDim.x * blockDim.x;
    float* pemb = S + OFF_PEMB;
    float* wemb = S + OFF_WEMB;
    for (int idx = i; idx < TT*BATCH*PE; idx += stride) {
        int tb = idx / PE, e = idx - tb*PE;
        pemb[idx] = pos_emb[pos[tb]*PE + e];
    }
    for (int idx = i; idx < TT*BATCH*WE; idx += stride) {
        int tb = idx / WE, e = idx - tb*WE;
        wemb[idx] = word_emb[word[tb]*WE + e];
    }
    // zero ph0, ph1, pc
    for (int idx = i; idx < 3*SZ_PH; idx += stride) S[OFF_PH0 + idx] = 0.f;
    // zero wh0a..wc1 (6 buffers)
    for (int idx = i; idx < 6*SZ_WH; idx += stride) S[OFF_WH0A + idx] = 0.f;
}

// ---------------- grid barrier ----------------
__device__ __forceinline__ void grid_bar()
{
    __threadfence();           // release: make this thread's writes visible
    __syncthreads();           // all threads fenced before arrival
    if (threadIdx.x == 0) {
        volatile unsigned* gen = &g_bar_gen;
        unsigned g = *gen;
        unsigned a = atomicAdd(&g_bar_cnt, 1u);
        if (a == GRID - 1u) {
            g_bar_cnt = 0u;
            __threadfence();
            atomicAdd(&g_bar_gen, 1u);
        } else {
            while (*gen == g) __nanosleep(64);
        }
    }
    __syncthreads();
    __threadfence();           // acquire: invalidate L1 before reading peers' data
}

// ---------------- A staging into padded smem ----------------
// sA layout: row b occupies (K/4+1) float4's; word addr = b*(K+4)+k -> conflict-free LDS.128
__device__ __forceinline__ void stage_if(const float* A, int K, float* sAdyn,
                                         const float* volatile* s_staged)
{
    if (*s_staged != A) {
        __syncthreads();
        int K4 = K >> 2;
        const float4* A4 = (const float4*)A;
        float4* S4 = (float4*)sAdyn;
        for (int i = threadIdx.x; i < 32*K4; i += TPB) {
            int row = i / K4, kq = i - row*K4;
            S4[row*(K4+1) + kq] = A4[row*K4 + kq];
        }
        if (threadIdx.x == 0) *s_staged = A;
        __syncthreads();
    }
}

// ---------------- per-warp 4-col K-slice accumulate ----------------
__device__ __forceinline__ void accum4(const float* __restrict__ W, int ldw, int wcol, int K,
                                       const int* n, int s, float* acc,
                                       const float* __restrict__ sAdyn)
{
    int lane = threadIdx.x & 31;
    int K4 = K >> 2;
    int Q  = K4 >> 2;                       // float4 groups per slice
    const float4* a4 = (const float4*)sAdyn + lane*(K4+1);
    const float* W0 = W + (size_t)n[0]*ldw + wcol;
    const float* W1 = W + (size_t)n[1]*ldw + wcol;
    const float* W2 = W + (size_t)n[2]*ldw + wcol;
    const float* W3 = W + (size_t)n[3]*ldw + wcol;
    int q0 = s*Q, q1 = q0 + Q;
    #pragma unroll 2
    for (int q = q0; q < q1; q++) {
        float4 a = a4[q];
        int k = q << 2;
        float4 w;
        w = *(const float4*)(W0 + k);
        acc[0] = fmaf(a.x,w.x, fmaf(a.y,w.y, fmaf(a.z,w.z, fmaf(a.w,w.w, acc[0]))));
        w = *(const float4*)(W1 + k);
        acc[1] = fmaf(a.x,w.x, fmaf(a.y,w.y, fmaf(a.z,w.z, fmaf(a.w,w.w, acc[1]))));
        w = *(const float4*)(W2 + k);
        acc[2] = fmaf(a.x,w.x, fmaf(a.y,w.y, fmaf(a.z,w.z, fmaf(a.w,w.w, acc[2]))));
        w = *(const float4*)(W3 + k);
        acc[3] = fmaf(a.x,w.x, fmaf(a.y,w.y, fmaf(a.z,w.z, fmaf(a.w,w.w, acc[3]))));
    }
}

// ---------------- persistent sequential-phase kernel ----------------
__global__ __launch_bounds__(TPB, 1) void persist_kernel(
    const float* __restrict__ w2p_W, const float* __restrict__ w2p_b,
    const float* __restrict__ p2w_W, const float* __restrict__ p2w_b,
    const float* __restrict__ p_Wih0, const float* __restrict__ p_Whh0,
    const float* __restrict__ w_Wih0, const float* __restrict__ w_Whh0,
    const float* __restrict__ w_Wih1, const float* __restrict__ w_Whh1,
    const float* __restrict__ w_bih1, const float* __restrict__ w_bhh1,
    float* __restrict__ S)
{
    extern __shared__ float sA[];
    __shared__ float red[4][16][33];
    __shared__ const float* volatile s_staged;

    float* gpseq = S + OFF_GPSEQ;
    float* gwseq = S + OFF_GWSEQ;
    float* phb[2]  = { S + OFF_PH0,  S + OFF_PH1 };
    float* pc    = S + OFF_PC;
    float* wh0b[2] = { S + OFF_WH0A, S + OFF_WH0B };
    float* wc0   = S + OFF_WC0;
    float* wh1b[2] = { S + OFF_WH1A, S + OFF_WH1B };
    float* wc1   = S + OFF_WC1;
    float* lastw = S + OFF_LASTW;
    float* lastp = S + OFF_LASTP;
    float* wg0h  = S + OFF_WG0H;
    float* wg1h  = S + OFF_WG1H;
    float* phseq = S + OFF_PHSEQ;
    float* whseq = S + OFF_WHSEQ;

    int lane = threadIdx.x & 31;
    int wrp  = threadIdx.x >> 5;     // 0..15
    int s    = wrp & 3;              // K-slice
    int cg   = wrp >> 2;             // col group (4 cols)

    if (threadIdx.x == 0) s_staged = nullptr;
    __syncthreads();

    int pp = 0, pw0 = 0, pw1 = 0;

    for (int t = 0; t < TT; t++) {
        const float* wh1c = wh1b[pw1];
        const float* wh0c = wh0b[pw0];

        // ===== S1: lastw (tanh), wg1h, wg0h =====
        for (int gid = blockIdx.x; gid < 576; gid += GRID) {
            const float* A; const float* W; float* dst; const float* bias;
            int n0, Ntot, epi;
            if (gid < 64)       { A=wh1c; W=w2p_W;  dst=lastw; bias=w2p_b; n0=gid*16;        Ntot=WH;   epi=1; }
            else if (gid < 320) { A=wh1c; W=w_Whh1; dst=wg1h;  bias=0;     n0=(gid-64)*16;   Ntot=4*WH; epi=0; }
            else                { A=wh0c; W=w_Whh0; dst=wg0h;  bias=0;     n0=(gid-320)*16;  Ntot=4*WH; epi=0; }
            stage_if(A, WH, sA, &s_staged);
            int n[4]; float acc[4] = {0,0,0,0};
            #pragma unroll
            for (int c = 0; c < 4; c++) n[c] = n0 + cg*4 + c;
            accum4(W, WH, 0, WH, n, s, acc, sA);
            #pragma unroll
            for (int c = 0; c < 4; c++) red[s][cg*4+c][lane] = acc[c];
            __syncthreads();
            {   // 512 threads: cc = wrp, b = lane
                float v = red[0][wrp][lane] + red[1][wrp][lane]
                        + red[2][wrp][lane] + red[3][wrp][lane];
                int nn = n0 + wrp;
                if (epi) dst[lane*Ntot + nn] = tanhf(v + bias[nn]);
                else     dst[lane*Ntot + nn] = v;
            }
            __syncthreads();
        }
        grid_bar();
        if (threadIdx.x == 0) s_staged = nullptr;
        __syncthreads();

        // ===== S2: POS gates + cell =====
        const float* phc = phb[pp];
        float* phn = phb[pp^1];
        for (int gid = blockIdx.x; gid < 64; gid += GRID) {
            int j0 = gid*4;
            int n[4]; float acc[4] = {0,0,0,0};
            #pragma unroll
            for (int c = 0; c < 4; c++) n[c] = cg*PH + j0 + c;   // gate=cg, jl=c
            stage_if(lastw, WH, sA, &s_staged);
            accum4(p_Wih0, PE+WH, PE, WH, n, s, acc, sA);
            stage_if(phc, PH, sA, &s_staged);
            accum4(p_Whh0, PH, 0, PH, n, s, acc, sA);
            #pragma unroll
            for (int c = 0; c < 4; c++) red[s][cg*4+c][lane] = acc[c];
            __syncthreads();
            if (threadIdx.x < 128) {
                int jl = wrp, b = lane;
                int j = j0 + jl;
                const float* pre = gpseq + ((size_t)t*BATCH + b)*4*PH;
                float g[4];
                #pragma unroll
                for (int gate = 0; gate < 4; gate++) {
                    int cc = gate*4 + jl;
                    g[gate] = red[0][cc][b] + red[1][cc][b] + red[2][cc][b] + red[3][cc][b]
                            + pre[gate*PH + j];
                }
                float si = sigf(g[0]), sf = sigf(g[1]), so = sigf(g[3]);
                int idx = b*PH + j;
                float cn = sf * pc[idx] + si * tanhf(g[2]);
                float hn = so * tanhf(cn);
                pc[idx] = cn; phn[idx] = hn;
                phseq[((size_t)t*BATCH + b)*PH + j] = hn;
            }
            __syncthreads();
        }
        grid_bar();
        if (threadIdx.x == 0) s_staged = nullptr;
        __syncthreads();

        // ===== S3: lastp = tanh(phn @ p2w^T + b) =====
        for (int gid = blockIdx.x; gid < 16; gid += GRID) {
            int n0 = gid*16;
            int n[4]; float acc[4] = {0,0,0,0};
            #pragma unroll
            for (int c = 0; c < 4; c++) n[c] = n0 + cg*4 + c;
            stage_if(phn, PH, sA, &s_staged);
            accum4(p2w_W, PH, 0, PH, n, s, acc, sA);
            #pragma unroll
            for (int c = 0; c < 4; c++) red[s][cg*4+c][lane] = acc[c];
            __syncthreads();
            {
                float v = red[0][wrp][lane] + red[1][wrp][lane]
                        + red[2][wrp][lane] + red[3][wrp][lane];
                int nn = n0 + wrp;
                lastp[lane*PH + nn] = tanhf(v + p2w_b[nn]);
            }
            __syncthreads();
        }
        grid_bar();
        if (threadIdx.x == 0) s_staged = nullptr;
        __syncthreads();

        // ===== S4: WORD L0 gates + cell =====
        float* wh0n = wh0b[pw0^1];
        for (int gid = blockIdx.x; gid < 256; gid += GRID) {
            int j0 = gid*4;
            int n[4]; float acc[4] = {0,0,0,0};
            #pragma unroll
            for (int c = 0; c < 4; c++) n[c] = cg*WH + j0 + c;
            stage_if(lastp, PH, sA, &s_staged);
            accum4(w_Wih0, WE+PH, WE, PH, n, s, acc, sA);
            #pragma unroll
            for (int c = 0; c < 4; c++) red[s][cg*4+c][lane] = acc[c];
            __syncthreads();
            if (threadIdx.x < 128) {
                int jl = wrp, b = lane;
                int j = j0 + jl;
                const float* pre = gwseq + ((size_t)t*BATCH + b)*4*WH;
                const float* hid = wg0h + (size_t)b*4*WH;
                float g[4];
                #pragma unroll
                for (int gate = 0; gate < 4; gate++) {
                    int cc = gate*4 + jl;
                    int nn = gate*WH + j;
                    g[gate] = red[0][cc][b] + red[1][cc][b] + red[2][cc][b] + red[3][cc][b]
                            + pre[nn] + hid[nn];
                }
                float si = sigf(g[0]), sf = sigf(g[1]), so = sigf(g[3]);
                int idx = b*WH + j;
                float cn = sf * wc0[idx] + si * tanhf(g[2]);
                float hn = so * tanhf(cn);
                wc0[idx] = cn; wh0n[idx] = hn;
            }
            __syncthreads();
        }
        grid_bar();
        if (threadIdx.x == 0) s_staged = nullptr;
        __syncthreads();
        pw0 ^= 1;

        // ===== S5: WORD L1 gates + cell =====
        float* wh1n = wh1b[pw1^1];
        const float* wh0new = wh0b[pw0];
        for (int gid = blockIdx.x; gid < 256; gid += GRID) {
            int j0 = gid*4;
            int n[4]; float acc[4] = {0,0,0,0};
            #pragma unroll
            for (int c = 0; c < 4; c++) n[c] = cg*WH + j0 + c;
            stage_if(wh0new, WH, sA, &s_staged);
            accum4(w_Wih1, WH, 0, WH, n, s, acc, sA);
            #pragma unroll
            for (int c = 0; c < 4; c++) red[s][cg*4+c][lane] = acc[c];
            __syncthreads();
            if (threadIdx.x < 128) {
                int jl = wrp, b = lane;
                int j = j0 + jl;
                const float* hid = wg1h + (size_t)b*4*WH;
                float g[4];
                #pragma unroll
                for (int gate = 0; gate < 4; gate++) {
                    int cc = gate*4 + jl;
                    int nn = gate*WH + j;
                    g[gate] = red[0][cc][b] + red[1][cc][b] + red[2][cc][b] + red[3][cc][b]
                            + hid[nn] + w_bih1[nn] + w_bhh1[nn];
                }
                float si = sigf(g[0]), sf = sigf(g[1]), so = sigf(g[3]);
                int idx = b*WH + j;
                float cn = sf * wc1[idx] + si * tanhf(g[2]);
                float hn = so * tanhf(cn);
                wc1[idx] = cn; wh1n[idx] = hn;
                whseq[((size_t)t*BATCH + b)*WH + j] = hn;
            }
            __syncthreads();
        }
        grid_bar();
        if (threadIdx.x == 0) s_staged = nullptr;
        __syncthreads();
        pw1 ^= 1;
        pp  ^= 1;
    }
}

// ---------------- big GEMM: C[M,N] = A[M,K] @ W[N, wcol:wcol+K]^T + b1 (+b2) ----------------
__global__ __launch_bounds__(256) void big_gemm(const float* __restrict__ A, int lda,
                                                const float* __restrict__ W, int ldw, int wcol,
                                                const float* __restrict__ bias1,
                                                const float* __restrict__ bias2,
                                                float* __restrict__ C, long ldc, int K)
{
    __shared__ float sAa[16][132];
    __shared__ float sW[16][68];
    int tx = threadIdx.x & 15, ty = threadIdx.x >> 4;
    int bm = blockIdx.y * 128, bn = blockIdx.x * 64;
    float acc[8][4];
    #pragma unroll
    for (int i = 0; i < 8; i++)
        #pragma unroll
        for (int j = 0; j < 4; j++) acc[i][j] = 0.f;

    for (int kt = 0; kt < K; kt += 16) {
        __syncthreads();
        #pragma unroll
        for (int i = 0; i < 2; i++) {
            int f = threadIdx.x + i*256;
            int row = f >> 2, kq = (f & 3) * 4;
            float4 v = *reinterpret_cast<const float4*>(A + (long)(bm+row)*lda + kt + kq);
            sAa[kq][row] = v.x; sAa[kq+1][row] = v.y; sAa[kq+2][row] = v.z; sAa[kq+3][row] = v.w;
        }
        {
            int f = threadIdx.x;
            int row = f >> 2, kq = (f & 3) * 4;
            float4 v = *reinterpret_cast<const float4*>(W + (long)(bn+row)*ldw + wcol + kt + kq);
            sW[kq][row] = v.x; sW[kq+1][row] = v.y; sW[kq+2][row] = v.z; sW[kq+3][row] = v.w;
        }
        __syncthreads();
        #pragma unroll
        for (int k = 0; k < 16; k++) {
            float4 a0 = *reinterpret_cast<float4*>(&sAa[k][ty*8]);
            float4 a1 = *reinterpret_cast<float4*>(&sAa[k][ty*8+4]);
            float4 w  = *reinterpret_cast<float4*>(&sW[k][tx*4]);
            float am[8] = {a0.x,a0.y,a0.z,a0.w,a1.x,a1.y,a1.z,a1.w};
            float wn[4] = {w.x,w.y,w.z,w.w};
            #pragma unroll
            for (int i = 0; i < 8; i++)
                #pragma unroll
                for (int j = 0; j < 4; j++)
                    acc[i][j] = fmaf(am[i], wn[j], acc[i][j]);
        }
    }

    float bv[4];
    #pragma unroll
    for (int j = 0; j < 4; j++) {
        int nn = bn + tx*4 + j;
        bv[j] = (bias1 ? bias1[nn] : 0.f) + (bias2 ? bias2[nn] : 0.f);
    }
    #pragma unroll
    for (int i = 0; i < 8; i++) {
        int m = bm + ty*8 + i;
        float4 o;
        o.x = acc[i][0] + bv[0]; o.y = acc[i][1] + bv[1];
        o.z = acc[i][2] + bv[2]; o.w = acc[i][3] + bv[3];
        *reinterpret_cast<float4*>(C + (long)m*ldc + bn + tx*4) = o;
    }
}

// ---------------- pos projection + log_softmax (48-way) ----------------
__global__ void pos_out_kernel(const float* __restrict__ phseq,
                               const float* __restrict__ proj_W,
                               const float* __restrict__ proj_b,
                               float* __restrict__ out)
{
    int row = blockIdx.x;
    const float* h = phseq + row * PH;
    __shared__ float sh[PH];
    __shared__ float logits[PV];
    __shared__ float lse;
    for (int i = threadIdx.x; i < PH; i += 64) sh[i] = h[i];
    __syncthreads();
    if (threadIdx.x < PV) {
        float s = proj_b[threadIdx.x];
        const float* wr = proj_W + threadIdx.x * PH;
        #pragma unroll 4
        for (int k = 0; k < PH; k++) s += sh[k] * wr[k];
        logits[threadIdx.x] = s;
    }
    __syncthreads();
    if (threadIdx.x == 0) {
        float m = -1e30f;
        for (int i = 0; i < PV; i++) m = fmaxf(m, logits[i]);
        float ssum = 0.f;
        for (int i = 0; i < PV; i++) ssum += expf(logits[i] - m);
        lse = m + logf(ssum);
    }
    __syncthreads();
    if (threadIdx.x < PV) out[row * PV + threadIdx.x] = logits[threadIdx.x] - lse;
}

// ---------------- in-place log_softmax over rows of WV ----------------
__global__ void word_lsm(float* __restrict__ out)
{
    int row = blockIdx.x;
    float* r = out + (long)row * WV;
    float m = -1e30f, s = 0.f;
    for (int i = threadIdx.x; i < WV; i += blockDim.x) {
        float v = r[i];
        if (v > m) { s = s * expf(m - v) + 1.f; m = v; }
        else       { s += expf(v - m); }
    }
    __shared__ float sm[256], ss[256];
    sm[threadIdx.x] = m; ss[threadIdx.x] = s;
    __syncthreads();
    for (int off = 128; off > 0; off >>= 1) {
        if (threadIdx.x < off) {
            float m1 = sm[threadIdx.x], s1 = ss[threadIdx.x];
            float m2 = sm[threadIdx.x + off], s2 = ss[threadIdx.x + off];
            float mm = fmaxf(m1, m2);
            sm[threadIdx.x] = mm;
            ss[threadIdx.x] = s1 * expf(m1 - mm) + s2 * expf(m2 - mm);
        }
        __syncthreads();
    }
    float lse = sm[0] + logf(ss[0]);
    for (int i = threadIdx.x; i < WV; i += blockDim.x) r[i] -= lse;
}

// ---------------- host orchestration ----------------
extern "C" void kernel_launch(void* const* d_in, const int* in_sizes, int n_in,
                              void* d_out, int out_size)
{
    (void)in_sizes; (void)n_in; (void)out_size;
    const int*   pos          = (const int*)  d_in[0];
    const int*   word         = (const int*)  d_in[1];
    const float* pos_emb_W    = (const float*)d_in[2];
    const float* word_emb_W   = (const float*)d_in[3];
    const float* w2p_W        = (const float*)d_in[4];
    const float* w2p_b        = (const float*)d_in[5];
    const float* p2w_W        = (const float*)d_in[6];
    const float* p2w_b        = (const float*)d_in[7];
    const float* p_Wih0       = (const float*)d_in[8];
    const float* p_Whh0       = (const float*)d_in[9];
    const float* p_bih0       = (const float*)d_in[10];
    const float* p_bhh0       = (const float*)d_in[11];
    const float* w_Wih0       = (const float*)d_in[12];
    const float* w_Whh0       = (const float*)d_in[13];
    const float* w_bih0       = (const float*)d_in[14];
    const float* w_bhh0       = (const float*)d_in[15];
    const float* w_Wih1       = (const float*)d_in[16];
    const float* w_Whh1       = (const float*)d_in[17];
    const float* w_bih1       = (const float*)d_in[18];
    const float* w_bhh1       = (const float*)d_in[19];
    const float* pos_proj_W   = (const float*)d_in[20];
    const float* pos_proj_b   = (const float*)d_in[21];
    const float* word_proj1_W = (const float*)d_in[22];
    const float* word_proj1_b = (const float*)d_in[23];
    const float* word_proj2_b = (const float*)d_in[24];
    float* out = (float*)d_out;

    float* S = nullptr;
    cudaGetSymbolAddress((void**)&S, g_scratch);
    float* pemb  = S + OFF_PEMB;
    float* wemb  = S + OFF_WEMB;
    float* gpseq = S + OFF_GPSEQ;
    float* gwseq = S + OFF_GWSEQ;
    float* phseq = S + OFF_PHSEQ;
    float* whseq = S + OFF_WHSEQ;
    float* he    = S + OFF_HE;

    static bool attr_set = false;
    if (!attr_set) {
        cudaFuncSetAttribute(persist_kernel, cudaFuncAttributeMaxDynamicSharedMemorySize, SMEM_DYN);
        attr_set = true;
    }

    init_kernel<<<256, 256>>>(pos, word, pos_emb_W, word_emb_W, S);

    // input-side gate precomputes (parallel over all t):
    big_gemm<<<dim3(4*PH/64, TT*BATCH/128), 256>>>(pemb, PE, p_Wih0, PE+WH, 0,
                                                   p_bih0, p_bhh0, gpseq, 4*PH, PE);
    big_gemm<<<dim3(4*WH/64, TT*BATCH/128), 256>>>(wemb, WE, w_Wih0, WE+PH, 0,
                                                   w_bih0, w_bhh0, gwseq, 4*WH, WE);

    // entire sequential phase in one persistent launch
    persist_kernel<<<GRID, TPB, SMEM_DYN>>>(
        w2p_W, w2p_b, p2w_W, p2w_b,
        p_Wih0, p_Whh0, w_Wih0, w_Whh0,
        w_Wih1, w_Whh1, w_bih1, w_bhh1, S);

    // Phase B outputs
    pos_out_kernel<<<TT*BATCH, 64>>>(phseq, pos_proj_W, pos_proj_b, out);

    big_gemm<<<dim3(WE/64, TT*BATCH/128), 256>>>(whseq, WH, word_proj1_W, WH, 0,
                                                 word_proj1_b, nullptr, he, WE, WH);
    float* wout = out + (long)TT*BATCH*PV;
    big_gemm<<<dim3(WV/64, TT*BATCH/128), 256>>>(he, WE, word_emb_W, WE, 0,
                                                 word_proj2_b, nullptr, wout, WV, WE);
    word_lsm<<<TT*BATCH, 256>>>(wout);
}

// round 4
// speedup vs baseline: 3.1421x; 1.1035x over previous
#include <cuda_runtime.h>
#include <cuda_bf16.h>
#include <math.h>

// ---------------- problem constants ----------------
#define TT 64
#define BATCH 32
#define PE 128
#define WE 512
#define PH 256
#define WH 1024
#define PV 48
#define WV 32000

#define GRID 148
#define TPB  512

// ---------------- scratch ----------------
#define SZ_PEMB   (TT*BATCH*PE)
#define SZ_WEMB   (TT*BATCH*WE)
#define SZ_GPSEQ  (TT*BATCH*4*PH)
#define SZ_GWSEQ  (TT*BATCH*4*WH)
#define SZ_PH     (BATCH*PH)
#define SZ_WH     (BATCH*WH)
#define SZ_G4WH   (BATCH*4*WH)
#define SZ_PHSEQ  (TT*BATCH*PH)
#define SZ_WHSEQ  (TT*BATCH*WH)
#define SZ_HE     (TT*BATCH*WE)

#define OFF_PEMB   0
#define OFF_WEMB   (OFF_PEMB + SZ_PEMB)
#define OFF_GPSEQ  (OFF_WEMB + SZ_WEMB)
#define OFF_GWSEQ  (OFF_GPSEQ + SZ_GPSEQ)
#define OFF_PH0    (OFF_GWSEQ + SZ_GWSEQ)
#define OFF_PH1    (OFF_PH0 + SZ_PH)
#define OFF_PC     (OFF_PH1 + SZ_PH)
#define OFF_WH0A   (OFF_PC + SZ_PH)
#define OFF_WH0B   (OFF_WH0A + SZ_WH)
#define OFF_WC0    (OFF_WH0B + SZ_WH)
#define OFF_WH1A   (OFF_WC0 + SZ_WH)
#define OFF_WH1B   (OFF_WH1A + SZ_WH)
#define OFF_WC1    (OFF_WH1B + SZ_WH)
#define OFF_LASTW  (OFF_WC1 + SZ_WH)
#define OFF_LASTP  (OFF_LASTW + SZ_WH)
#define OFF_WG0H   (OFF_LASTP + SZ_PH)
#define OFF_WG1H   (OFF_WG0H + SZ_G4WH)
#define OFF_PHSEQ  (OFF_WG1H + SZ_G4WH)
#define OFF_WHSEQ  (OFF_PHSEQ + SZ_PHSEQ)
#define OFF_HE     (OFF_WHSEQ + SZ_WHSEQ)
#define SCRATCH_TOTAL (OFF_HE + SZ_HE)

__device__ float g_scratch[SCRATCH_TOTAL];
__device__ unsigned g_bar_cnt = 0;
__device__ unsigned g_bar_gen = 0;

// bf16 operands for the tensor-core vocab GEMM
__device__ __nv_bfloat16 g_wemb_bf[(size_t)WV * WE];
__device__ __nv_bfloat16 g_he_bf[(size_t)TT * BATCH * WE];

// dynamic smem for persist kernel: 32 rows x (1024/4+1) float4
#define SMEM_DYN (32 * 257 * 16)

__device__ __forceinline__ float sigf(float x) { return 1.f / (1.f + expf(-x)); }

// ---------------- init ----------------
__global__ void init_kernel(const int* __restrict__ pos, const int* __restrict__ word,
                            const float* __restrict__ pos_emb, const float* __restrict__ word_emb,
                            float* __restrict__ S)
{
    int i = blockIdx.x * blockDim.x + threadIdx.x;
    int stride = gridDim.x * blockDim.x;
    float* pemb = S + OFF_PEMB;
    float* wemb = S + OFF_WEMB;
    for (int idx = i; idx < TT*BATCH*PE; idx += stride) {
        int tb = idx / PE, e = idx - tb*PE;
        pemb[idx] = pos_emb[pos[tb]*PE + e];
    }
    for (int idx = i; idx < TT*BATCH*WE; idx += stride) {
        int tb = idx / WE, e = idx - tb*WE;
        wemb[idx] = word_emb[word[tb]*WE + e];
    }
    for (int idx = i; idx < 3*SZ_PH; idx += stride) S[OFF_PH0 + idx] = 0.f;
    for (int idx = i; idx < 6*SZ_WH; idx += stride) S[OFF_WH0A + idx] = 0.f;
}

// ---------------- fp32 -> bf16 conversion (vectorized) ----------------
__global__ void conv_bf16(const float* __restrict__ src, __nv_bfloat16* __restrict__ dst,
                          int n4)
{
    int i = blockIdx.x * blockDim.x + threadIdx.x;
    int st = gridDim.x * blockDim.x;
    const float4* s4 = (const float4*)src;
    for (; i < n4; i += st) {
        float4 v = s4[i];
        __nv_bfloat162 lo = __floats2bfloat162_rn(v.x, v.y);
        __nv_bfloat162 hi = __floats2bfloat162_rn(v.z, v.w);
        *(__nv_bfloat162*)(dst + (size_t)i*4)     = lo;
        *(__nv_bfloat162*)(dst + (size_t)i*4 + 2) = hi;
    }
}

// ---------------- grid barrier ----------------
__device__ __forceinline__ void grid_bar()
{
    __threadfence();
    __syncthreads();
    if (threadIdx.x == 0) {
        volatile unsigned* gen = &g_bar_gen;
        unsigned g = *gen;
        unsigned a = atomicAdd(&g_bar_cnt, 1u);
        if (a == GRID - 1u) {
            g_bar_cnt = 0u;
            __threadfence();
            atomicAdd(&g_bar_gen, 1u);
        } else {
            while (*gen == g) __nanosleep(64);
        }
    }
    __syncthreads();
    __threadfence();
}

// ---------------- A staging into padded smem ----------------
__device__ __forceinline__ void stage_if(const float* A, int K, float* sAdyn,
                                         const float* volatile* s_staged)
{
    if (*s_staged != A) {
        __syncthreads();
        int K4 = K >> 2;
        const float4* A4 = (const float4*)A;
        float4* S4 = (float4*)sAdyn;
        for (int i = threadIdx.x; i < 32*K4; i += TPB) {
            int row = i / K4, kq = i - row*K4;
            S4[row*(K4+1) + kq] = A4[row*K4 + kq];
        }
        if (threadIdx.x == 0) *s_staged = A;
        __syncthreads();
    }
}

// ---------------- per-warp 4-col K-slice accumulate ----------------
__device__ __forceinline__ void accum4(const float* __restrict__ W, int ldw, int wcol, int K,
                                       const int* n, int s, float* acc,
                                       const float* __restrict__ sAdyn)
{
    int lane = threadIdx.x & 31;
    int K4 = K >> 2;
    int Q  = K4 >> 2;
    const float4* a4 = (const float4*)sAdyn + lane*(K4+1);
    const float* W0 = W + (size_t)n[0]*ldw + wcol;
    const float* W1 = W + (size_t)n[1]*ldw + wcol;
    const float* W2 = W + (size_t)n[2]*ldw + wcol;
    const float* W3 = W + (size_t)n[3]*ldw + wcol;
    int q0 = s*Q, q1 = q0 + Q;
    #pragma unroll 2
    for (int q = q0; q < q1; q++) {
        float4 a = a4[q];
        int k = q << 2;
        float4 w;
        w = *(const float4*)(W0 + k);
        acc[0] = fmaf(a.x,w.x, fmaf(a.y,w.y, fmaf(a.z,w.z, fmaf(a.w,w.w, acc[0]))));
        w = *(const float4*)(W1 + k);
        acc[1] = fmaf(a.x,w.x, fmaf(a.y,w.y, fmaf(a.z,w.z, fmaf(a.w,w.w, acc[1]))));
        w = *(const float4*)(W2 + k);
        acc[2] = fmaf(a.x,w.x, fmaf(a.y,w.y, fmaf(a.z,w.z, fmaf(a.w,w.w, acc[2]))));
        w = *(const float4*)(W3 + k);
        acc[3] = fmaf(a.x,w.x, fmaf(a.y,w.y, fmaf(a.z,w.z, fmaf(a.w,w.w, acc[3]))));
    }
}

// ---------------- persistent sequential-phase kernel ----------------
__global__ __launch_bounds__(TPB, 1) void persist_kernel(
    const float* __restrict__ w2p_W, const float* __restrict__ w2p_b,
    const float* __restrict__ p2w_W, const float* __restrict__ p2w_b,
    const float* __restrict__ p_Wih0, const float* __restrict__ p_Whh0,
    const float* __restrict__ w_Wih0, const float* __restrict__ w_Whh0,
    const float* __restrict__ w_Wih1, const float* __restrict__ w_Whh1,
    const float* __restrict__ w_bih1, const float* __restrict__ w_bhh1,
    float* __restrict__ S)
{
    extern __shared__ float sA[];
    __shared__ float red[4][16][33];
    __shared__ const float* volatile s_staged;

    float* gpseq = S + OFF_GPSEQ;
    float* gwseq = S + OFF_GWSEQ;
    float* phb[2]  = { S + OFF_PH0,  S + OFF_PH1 };
    float* pc    = S + OFF_PC;
    float* wh0b[2] = { S + OFF_WH0A, S + OFF_WH0B };
    float* wc0   = S + OFF_WC0;
    float* wh1b[2] = { S + OFF_WH1A, S + OFF_WH1B };
    float* wc1   = S + OFF_WC1;
    float* lastw = S + OFF_LASTW;
    float* lastp = S + OFF_LASTP;
    float* wg0h  = S + OFF_WG0H;
    float* wg1h  = S + OFF_WG1H;
    float* phseq = S + OFF_PHSEQ;
    float* whseq = S + OFF_WHSEQ;

    int lane = threadIdx.x & 31;
    int wrp  = threadIdx.x >> 5;
    int s    = wrp & 3;
    int cg   = wrp >> 2;

    if (threadIdx.x == 0) s_staged = nullptr;
    __syncthreads();

    int pp = 0, pw0 = 0, pw1 = 0;

    for (int t = 0; t < TT; t++) {
        const float* wh1c = wh1b[pw1];
        const float* wh0c = wh0b[pw0];

        // ===== S1: lastw (tanh), wg1h, wg0h =====
        for (int gid = blockIdx.x; gid < 576; gid += GRID) {
            const float* A; const float* W; float* dst; const float* bias;
            int n0, Ntot, epi;
            if (gid < 64)       { A=wh1c; W=w2p_W;  dst=lastw; bias=w2p_b; n0=gid*16;        Ntot=WH;   epi=1; }
            else if (gid < 320) { A=wh1c; W=w_Whh1; dst=wg1h;  bias=0;     n0=(gid-64)*16;   Ntot=4*WH; epi=0; }
            else                { A=wh0c; W=w_Whh0; dst=wg0h;  bias=0;     n0=(gid-320)*16;  Ntot=4*WH; epi=0; }
            stage_if(A, WH, sA, &s_staged);
            int n[4]; float acc[4] = {0,0,0,0};
            #pragma unroll
            for (int c = 0; c < 4; c++) n[c] = n0 + cg*4 + c;
            accum4(W, WH, 0, WH, n, s, acc, sA);
            #pragma unroll
            for (int c = 0; c < 4; c++) red[s][cg*4+c][lane] = acc[c];
            __syncthreads();
            {
                float v = red[0][wrp][lane] + red[1][wrp][lane]
                        + red[2][wrp][lane] + red[3][wrp][lane];
                int nn = n0 + wrp;
                if (epi) dst[lane*Ntot + nn] = tanhf(v + bias[nn]);
                else     dst[lane*Ntot + nn] = v;
            }
            __syncthreads();
        }
        grid_bar();
        if (threadIdx.x == 0) s_staged = nullptr;
        __syncthreads();

        // ===== S2: POS gates + cell =====
        const float* phc = phb[pp];
        float* phn = phb[pp^1];
        for (int gid = blockIdx.x; gid < 64; gid += GRID) {
            int j0 = gid*4;
            int n[4]; float acc[4] = {0,0,0,0};
            #pragma unroll
            for (int c = 0; c < 4; c++) n[c] = cg*PH + j0 + c;
            stage_if(lastw, WH, sA, &s_staged);
            accum4(p_Wih0, PE+WH, PE, WH, n, s, acc, sA);
            stage_if(phc, PH, sA, &s_staged);
            accum4(p_Whh0, PH, 0, PH, n, s, acc, sA);
            #pragma unroll
            for (int c = 0; c < 4; c++) red[s][cg*4+c][lane] = acc[c];
            __syncthreads();
            if (threadIdx.x < 128) {
                int jl = wrp, b = lane;
                int j = j0 + jl;
                const float* pre = gpseq + ((size_t)t*BATCH + b)*4*PH;
                float g[4];
                #pragma unroll
                for (int gate = 0; gate < 4; gate++) {
                    int cc = gate*4 + jl;
                    g[gate] = red[0][cc][b] + red[1][cc][b] + red[2][cc][b] + red[3][cc][b]
                            + pre[gate*PH + j];
                }
                float si = sigf(g[0]), sf = sigf(g[1]), so = sigf(g[3]);
                int idx = b*PH + j;
                float cn = sf * pc[idx] + si * tanhf(g[2]);
                float hn = so * tanhf(cn);
                pc[idx] = cn; phn[idx] = hn;
                phseq[((size_t)t*BATCH + b)*PH + j] = hn;
            }
            __syncthreads();
        }
        grid_bar();
        if (threadIdx.x == 0) s_staged = nullptr;
        __syncthreads();

        // ===== S3: lastp = tanh(phn @ p2w^T + b) =====
        for (int gid = blockIdx.x; gid < 16; gid += GRID) {
            int n0 = gid*16;
            int n[4]; float acc[4] = {0,0,0,0};
            #pragma unroll
            for (int c = 0; c < 4; c++) n[c] = n0 + cg*4 + c;
            stage_if(phn, PH, sA, &s_staged);
            accum4(p2w_W, PH, 0, PH, n, s, acc, sA);
            #pragma unroll
            for (int c = 0; c < 4; c++) red[s][cg*4+c][lane] = acc[c];
            __syncthreads();
            {
                float v = red[0][wrp][lane] + red[1][wrp][lane]
                        + red[2][wrp][lane] + red[3][wrp][lane];
                int nn = n0 + wrp;
                lastp[lane*PH + nn] = tanhf(v + p2w_b[nn]);
            }
            __syncthreads();
        }
        grid_bar();
        if (threadIdx.x == 0) s_staged = nullptr;
        __syncthreads();

        // ===== S4: WORD L0 gates + cell =====
        float* wh0n = wh0b[pw0^1];
        for (int gid = blockIdx.x; gid < 256; gid += GRID) {
            int j0 = gid*4;
            int n[4]; float acc[4] = {0,0,0,0};
            #pragma unroll
            for (int c = 0; c < 4; c++) n[c] = cg*WH + j0 + c;
            stage_if(lastp, PH, sA, &s_staged);
            accum4(w_Wih0, WE+PH, WE, PH, n, s, acc, sA);
            #pragma unroll
            for (int c = 0; c < 4; c++) red[s][cg*4+c][lane] = acc[c];
            __syncthreads();
            if (threadIdx.x < 128) {
                int jl = wrp, b = lane;
                int j = j0 + jl;
                const float* pre = gwseq + ((size_t)t*BATCH + b)*4*WH;
                const float* hid = wg0h + (size_t)b*4*WH;
                float g[4];
                #pragma unroll
                for (int gate = 0; gate < 4; gate++) {
                    int cc = gate*4 + jl;
                    int nn = gate*WH + j;
                    g[gate] = red[0][cc][b] + red[1][cc][b] + red[2][cc][b] + red[3][cc][b]
                            + pre[nn] + hid[nn];
                }
                float si = sigf(g[0]), sf = sigf(g[1]), so = sigf(g[3]);
                int idx = b*WH + j;
                float cn = sf * wc0[idx] + si * tanhf(g[2]);
                float hn = so * tanhf(cn);
                wc0[idx] = cn; wh0n[idx] = hn;
            }
            __syncthreads();
        }
        grid_bar();
        if (threadIdx.x == 0) s_staged = nullptr;
        __syncthreads();
        pw0 ^= 1;

        // ===== S5: WORD L1 gates + cell =====
        float* wh1n = wh1b[pw1^1];
        const float* wh0new = wh0b[pw0];
        for (int gid = blockIdx.x; gid < 256; gid += GRID) {
            int j0 = gid*4;
            int n[4]; float acc[4] = {0,0,0,0};
            #pragma unroll
            for (int c = 0; c < 4; c++) n[c] = cg*WH + j0 + c;
            stage_if(wh0new, WH, sA, &s_staged);
            accum4(w_Wih1, WH, 0, WH, n, s, acc, sA);
            #pragma unroll
            for (int c = 0; c < 4; c++) red[s][cg*4+c][lane] = acc[c];
            __syncthreads();
            if (threadIdx.x < 128) {
                int jl = wrp, b = lane;
                int j = j0 + jl;
                const float* hid = wg1h + (size_t)b*4*WH;
                float g[4];
                #pragma unroll
                for (int gate = 0; gate < 4; gate++) {
                    int cc = gate*4 + jl;
                    int nn = gate*WH + j;
                    g[gate] = red[0][cc][b] + red[1][cc][b] + red[2][cc][b] + red[3][cc][b]
                            + hid[nn] + w_bih1[nn] + w_bhh1[nn];
                }
                float si = sigf(g[0]), sf = sigf(g[1]), so = sigf(g[3]);
                int idx = b*WH + j;
                float cn = sf * wc1[idx] + si * tanhf(g[2]);
                float hn = so * tanhf(cn);
                wc1[idx] = cn; wh1n[idx] = hn;
                whseq[((size_t)t*BATCH + b)*WH + j] = hn;
            }
            __syncthreads();
        }
        grid_bar();
        if (threadIdx.x == 0) s_staged = nullptr;
        __syncthreads();
        pw1 ^= 1;
        pp  ^= 1;
    }
}

// ---------------- big GEMM (fp32): C[M,N] = A[M,K] @ W[N, wcol:wcol+K]^T + b1 (+b2) ----------------
__global__ __launch_bounds__(256) void big_gemm(const float* __restrict__ A, int lda,
                                                const float* __restrict__ W, int ldw, int wcol,
                                                const float* __restrict__ bias1,
                                                const float* __restrict__ bias2,
                                                float* __restrict__ C, long ldc, int K)
{
    __shared__ float sAa[16][132];
    __shared__ float sW[16][68];
    int tx = threadIdx.x & 15, ty = threadIdx.x >> 4;
    int bm = blockIdx.y * 128, bn = blockIdx.x * 64;
    float acc[8][4];
    #pragma unroll
    for (int i = 0; i < 8; i++)
        #pragma unroll
        for (int j = 0; j < 4; j++) acc[i][j] = 0.f;

    for (int kt = 0; kt < K; kt += 16) {
        __syncthreads();
        #pragma unroll
        for (int i = 0; i < 2; i++) {
            int f = threadIdx.x + i*256;
            int row = f >> 2, kq = (f & 3) * 4;
            float4 v = *reinterpret_cast<const float4*>(A + (long)(bm+row)*lda + kt + kq);
            sAa[kq][row] = v.x; sAa[kq+1][row] = v.y; sAa[kq+2][row] = v.z; sAa[kq+3][row] = v.w;
        }
        {
            int f = threadIdx.x;
            int row = f >> 2, kq = (f & 3) * 4;
            float4 v = *reinterpret_cast<const float4*>(W + (long)(bn+row)*ldw + wcol + kt + kq);
            sW[kq][row] = v.x; sW[kq+1][row] = v.y; sW[kq+2][row] = v.z; sW[kq+3][row] = v.w;
        }
        __syncthreads();
        #pragma unroll
        for (int k = 0; k < 16; k++) {
            float4 a0 = *reinterpret_cast<float4*>(&sAa[k][ty*8]);
            float4 a1 = *reinterpret_cast<float4*>(&sAa[k][ty*8+4]);
            float4 w  = *reinterpret_cast<float4*>(&sW[k][tx*4]);
            float am[8] = {a0.x,a0.y,a0.z,a0.w,a1.x,a1.y,a1.z,a1.w};
            float wn[4] = {w.x,w.y,w.z,w.w};
            #pragma unroll
            for (int i = 0; i < 8; i++)
                #pragma unroll
                for (int j = 0; j < 4; j++)
                    acc[i][j] = fmaf(am[i], wn[j], acc[i][j]);
        }
    }

    float bv[4];
    #pragma unroll
    for (int j = 0; j < 4; j++) {
        int nn = bn + tx*4 + j;
        bv[j] = (bias1 ? bias1[nn] : 0.f) + (bias2 ? bias2[nn] : 0.f);
    }
    #pragma unroll
    for (int i = 0; i < 8; i++) {
        int m = bm + ty*8 + i;
        float4 o;
        o.x = acc[i][0] + bv[0]; o.y = acc[i][1] + bv[1];
        o.z = acc[i][2] + bv[2]; o.w = acc[i][3] + bv[3];
        *reinterpret_cast<float4*>(C + (long)m*ldc + bn + tx*4) = o;
    }
}

// ---------------- tensor-core vocab GEMM ----------------
// C[2048, 32000] = Abf[2048,512] @ Bbf[32000,512]^T + bias
__device__ __forceinline__ void mma16816(float* c, const unsigned* a, const unsigned* b)
{
    asm volatile("mma.sync.aligned.m16n8k16.row.col.f32.bf16.bf16.f32 "
        "{%0,%1,%2,%3}, {%4,%5,%6,%7}, {%8,%9}, {%0,%1,%2,%3};"
        : "+f"(c[0]), "+f"(c[1]), "+f"(c[2]), "+f"(c[3])
        : "r"(a[0]), "r"(a[1]), "r"(a[2]), "r"(a[3]), "r"(b[0]), "r"(b[1]));
}

__device__ __forceinline__ void ldsm4(unsigned* r, const void* p)
{
    unsigned ad = (unsigned)__cvta_generic_to_shared(p);
    asm volatile("ldmatrix.sync.aligned.m8n8.x4.shared.b16 {%0,%1,%2,%3}, [%4];"
        : "=r"(r[0]), "=r"(r[1]), "=r"(r[2]), "=r"(r[3]) : "r"(ad));
}

__global__ __launch_bounds__(256) void vocab_mma(const __nv_bfloat16* __restrict__ Abf,
                                                 const __nv_bfloat16* __restrict__ Bbf,
                                                 const float* __restrict__ bias,
                                                 float* __restrict__ C)
{
    __shared__ __nv_bfloat16 sAm[128][40];   // 80B rows -> conflict-free ldmatrix
    __shared__ __nv_bfloat16 sBm[128][40];
    int tid = threadIdx.x;
    int lane = tid & 31, wid = tid >> 5;
    int wm = wid >> 2, wn = wid & 3;        // 2 x 4 warp grid; warp tile 64x32
    int bm = blockIdx.y * 128, bn = blockIdx.x * 128;

    float acc[4][4][4] = {};

    for (int kt = 0; kt < WE; kt += 32) {
        __syncthreads();
        #pragma unroll
        for (int c = 0; c < 2; c++) {
            int ch = tid + c*256;           // 0..511
            int row = ch >> 2, seg = (ch & 3) * 8;
            *(uint4*)&sAm[row][seg] = *(const uint4*)&Abf[(size_t)(bm+row)*WE + kt + seg];
            *(uint4*)&sBm[row][seg] = *(const uint4*)&Bbf[(size_t)(bn+row)*WE + kt + seg];
        }
        __syncthreads();
        #pragma unroll
        for (int k16 = 0; k16 < 2; k16++) {
            unsigned afrag[4][4], bfrag[4][2];
            #pragma unroll
            for (int mf = 0; mf < 4; mf++) {
                int row = wm*64 + mf*16 + (lane & 15);
                int col = k16*16 + (lane >> 4) * 8;
                ldsm4(afrag[mf], &sAm[row][col]);
            }
            #pragma unroll
            for (int np = 0; np < 2; np++) {
                int row = wn*32 + np*16 + (lane & 7) + ((lane >> 4) << 3);
                int col = k16*16 + (((lane >> 3) & 1) << 3);
                unsigned r[4];
                ldsm4(r, &sBm[row][col]);
                bfrag[np*2][0]   = r[0]; bfrag[np*2][1]   = r[1];
                bfrag[np*2+1][0] = r[2]; bfrag[np*2+1][1] = r[3];
            }
            #pragma unroll
            for (int mf = 0; mf < 4; mf++)
                #pragma unroll
                for (int nf = 0; nf < 4; nf++)
                    mma16816(acc[mf][nf], afrag[mf], bfrag[nf]);
        }
    }

    int tg = lane >> 2;
    int tc = (lane & 3) * 2;
    #pragma unroll
    for (int nf = 0; nf < 4; nf++) {
        int n = bn + wn*32 + nf*8 + tc;
        float b0 = bias[n], b1 = bias[n+1];
        #pragma unroll
        for (int mf = 0; mf < 4; mf++) {
            int m0 = bm + wm*64 + mf*16 + tg;
            float2 v0 = { acc[mf][nf][0] + b0, acc[mf][nf][1] + b1 };
            float2 v1 = { acc[mf][nf][2] + b0, acc[mf][nf][3] + b1 };
            *(float2*)&C[(size_t)m0*WV + n]     = v0;
            *(float2*)&C[(size_t)(m0+8)*WV + n] = v1;
        }
    }
}

// ---------------- pos projection + log_softmax (48-way) ----------------
__global__ void pos_out_kernel(const float* __restrict__ phseq,
                               const float* __restrict__ proj_W,
                               const float* __restrict__ proj_b,
                               float* __restrict__ out)
{
    int row = blockIdx.x;
    const float* h = phseq + row * PH;
    __shared__ float sh[PH];
    __shared__ float logits[PV];
    __shared__ float lse;
    for (int i = threadIdx.x; i < PH; i += 64) sh[i] = h[i];
    __syncthreads();
    if (threadIdx.x < PV) {
        float s = proj_b[threadIdx.x];
        const float* wr = proj_W + threadIdx.x * PH;
        #pragma unroll 4
        for (int k = 0; k < PH; k++) s += sh[k] * wr[k];
        logits[threadIdx.x] = s;
    }
    __syncthreads();
    if (threadIdx.x == 0) {
        float m = -1e30f;
        for (int i = 0; i < PV; i++) m = fmaxf(m, logits[i]);
        float ssum = 0.f;
        for (int i = 0; i < PV; i++) ssum += expf(logits[i] - m);
        lse = m + logf(ssum);
    }
    __syncthreads();
    if (threadIdx.x < PV) out[row * PV + threadIdx.x] = logits[threadIdx.x] - lse;
}

// ---------------- in-place log_softmax over rows of WV ----------------
__global__ void word_lsm(float* __restrict__ out)
{
    int row = blockIdx.x;
    float* r = out + (long)row * WV;
    float m = -1e30f, s = 0.f;
    for (int i = threadIdx.x; i < WV; i += blockDim.x) {
        float v = r[i];
        if (v > m) { s = s * expf(m - v) + 1.f; m = v; }
        else       { s += expf(v - m); }
    }
    __shared__ float sm[256], ss[256];
    sm[threadIdx.x] = m; ss[threadIdx.x] = s;
    __syncthreads();
    for (int off = 128; off > 0; off >>= 1) {
        if (threadIdx.x < off) {
            float m1 = sm[threadIdx.x], s1 = ss[threadIdx.x];
            float m2 = sm[threadIdx.x + off], s2 = ss[threadIdx.x + off];
            float mm = fmaxf(m1, m2);
            sm[threadIdx.x] = mm;
            ss[threadIdx.x] = s1 * expf(m1 - mm) + s2 * expf(m2 - mm);
        }
        __syncthreads();
    }
    float lse = sm[0] + logf(ss[0]);
    for (int i = threadIdx.x; i < WV; i += blockDim.x) r[i] -= lse;
}

// ---------------- host orchestration ----------------
extern "C" void kernel_launch(void* const* d_in, const int* in_sizes, int n_in,
                              void* d_out, int out_size)
{
    (void)in_sizes; (void)n_in; (void)out_size;
    const int*   pos          = (const int*)  d_in[0];
    const int*   word         = (const int*)  d_in[1];
    const float* pos_emb_W    = (const float*)d_in[2];
    const float* word_emb_W   = (const float*)d_in[3];
    const float* w2p_W        = (const float*)d_in[4];
    const float* w2p_b        = (const float*)d_in[5];
    const float* p2w_W        = (const float*)d_in[6];
    const float* p2w_b        = (const float*)d_in[7];
    const float* p_Wih0       = (const float*)d_in[8];
    const float* p_Whh0       = (const float*)d_in[9];
    const float* p_bih0       = (const float*)d_in[10];
    const float* p_bhh0       = (const float*)d_in[11];
    const float* w_Wih0       = (const float*)d_in[12];
    const float* w_Whh0       = (const float*)d_in[13];
    const float* w_bih0       = (const float*)d_in[14];
    const float* w_bhh0       = (const float*)d_in[15];
    const float* w_Wih1       = (const float*)d_in[16];
    const float* w_Whh1       = (const float*)d_in[17];
    const float* w_bih1       = (const float*)d_in[18];
    const float* w_bhh1       = (const float*)d_in[19];
    const float* pos_proj_W   = (const float*)d_in[20];
    const float* pos_proj_b   = (const float*)d_in[21];
    const float* word_proj1_W = (const float*)d_in[22];
    const float* word_proj1_b = (const float*)d_in[23];
    const float* word_proj2_b = (const float*)d_in[24];
    float* out = (float*)d_out;

    float* S = nullptr;
    cudaGetSymbolAddress((void**)&S, g_scratch);
    __nv_bfloat16* wemb_bf = nullptr;
    cudaGetSymbolAddress((void**)&wemb_bf, g_wemb_bf);
    __nv_bfloat16* he_bf = nullptr;
    cudaGetSymbolAddress((void**)&he_bf, g_he_bf);

    float* pemb  = S + OFF_PEMB;
    float* wemb  = S + OFF_WEMB;
    float* gpseq = S + OFF_GPSEQ;
    float* gwseq = S + OFF_GWSEQ;
    float* phseq = S + OFF_PHSEQ;
    float* whseq = S + OFF_WHSEQ;
    float* he    = S + OFF_HE;

    static bool attr_set = false;
    if (!attr_set) {
        cudaFuncSetAttribute(persist_kernel, cudaFuncAttributeMaxDynamicSharedMemorySize, SMEM_DYN);
        attr_set = true;
    }

    init_kernel<<<256, 256>>>(pos, word, pos_emb_W, word_emb_W, S);

    // convert tied embedding matrix to bf16 (independent of everything else)
    conv_bf16<<<2048, 256>>>(word_emb_W, wemb_bf, (int)((size_t)WV*WE/4));

    // input-side gate precomputes (parallel over all t):
    big_gemm<<<dim3(4*PH/64, TT*BATCH/128), 256>>>(pemb, PE, p_Wih0, PE+WH, 0,
                                                   p_bih0, p_bhh0, gpseq, 4*PH, PE);
    big_gemm<<<dim3(4*WH/64, TT*BATCH/128), 256>>>(wemb, WE, w_Wih0, WE+PH, 0,
                                                   w_bih0, w_bhh0, gwseq, 4*WH, WE);

    // entire sequential phase in one persistent launch
    persist_kernel<<<GRID, TPB, SMEM_DYN>>>(
        w2p_W, w2p_b, p2w_W, p2w_b,
        p_Wih0, p_Whh0, w_Wih0, w_Whh0,
        w_Wih1, w_Whh1, w_bih1, w_bhh1, S);

    // Phase B outputs
    pos_out_kernel<<<TT*BATCH, 64>>>(phseq, pos_proj_W, pos_proj_b, out);

    // he[2048,512] = whseq @ word_proj1_W^T + b  (fp32)
    big_gemm<<<dim3(WE/64, TT*BATCH/128), 256>>>(whseq, WH, word_proj1_W, WH, 0,
                                                 word_proj1_b, nullptr, he, WE, WH);
    // he -> bf16
    conv_bf16<<<1024, 256>>>(he, he_bf, (int)((size_t)TT*BATCH*WE/4));

    // logits = he_bf @ wemb_bf^T + b2  (tensor cores)
    float* wout = out + (long)TT*BATCH*PV;
    vocab_mma<<<dim3(WV/128, TT*BATCH/128), 256>>>(he_bf, wemb_bf, word_proj2_b, wout);
    word_lsm<<<TT*BATCH, 256>>>(wout);
}

// round 6
// speedup vs baseline: 3.3511x; 1.0665x over previous
#include <cuda_runtime.h>
#include <cuda_bf16.h>
#include <math.h>

// ---------------- problem constants ----------------
#define TT 64
#define BATCH 32
#define PE 128
#define WE 512
#define PH 256
#define WH 1024
#define PV 48
#define WV 32000

#define GRID 148
#define TPB  512

// ---------------- scratch ----------------
#define SZ_PEMB   (TT*BATCH*PE)
#define SZ_WEMB   (TT*BATCH*WE)
#define SZ_GPSEQ  (TT*BATCH*4*PH)
#define SZ_GWSEQ  (TT*BATCH*4*WH)
#define SZ_PH     (BATCH*PH)
#define SZ_WH     (BATCH*WH)
#define SZ_G4WH   (BATCH*4*WH)
#define SZ_PHSEQ  (TT*BATCH*PH)
#define SZ_WHSEQ  (TT*BATCH*WH)
#define SZ_HE     (TT*BATCH*WE)

#define OFF_PEMB   0
#define OFF_WEMB   (OFF_PEMB + SZ_PEMB)
#define OFF_GPSEQ  (OFF_WEMB + SZ_WEMB)
#define OFF_GWSEQ  (OFF_GPSEQ + SZ_GPSEQ)
#define OFF_PH0    (OFF_GWSEQ + SZ_GWSEQ)
#define OFF_PH1    (OFF_PH0 + SZ_PH)
#define OFF_PC     (OFF_PH1 + SZ_PH)
#define OFF_WH0A   (OFF_PC + SZ_PH)
#define OFF_WH0B   (OFF_WH0A + SZ_WH)
#define OFF_WC0    (OFF_WH0B + SZ_WH)
#define OFF_WH1A   (OFF_WC0 + SZ_WH)
#define OFF_WH1B   (OFF_WH1A + SZ_WH)
#define OFF_WC1    (OFF_WH1B + SZ_WH)
#define OFF_LASTW  (OFF_WC1 + SZ_WH)
#define OFF_LASTP  (OFF_LASTW + SZ_WH)
#define OFF_WG0H   (OFF_LASTP + SZ_PH)
#define OFF_WG1H   (OFF_WG0H + SZ_G4WH)
#define OFF_PHSEQ  (OFF_WG1H + SZ_G4WH)
#define OFF_WHSEQ  (OFF_PHSEQ + SZ_PHSEQ)
#define OFF_HE     (OFF_WHSEQ + SZ_WHSEQ)
#define SCRATCH_TOTAL (OFF_HE + SZ_HE)

__device__ float g_scratch[SCRATCH_TOTAL];
__device__ unsigned g_bar_cnt = 0;
__device__ unsigned g_bar_gen = 0;

// bf16 operands for the tensor-core vocab GEMM
__device__ __nv_bfloat16 g_wemb_bf[(size_t)WV * WE];
__device__ __nv_bfloat16 g_he_bf[(size_t)TT * BATCH * WE];

// dynamic smem for persist kernel: 32 rows x (1024/4+1) float4
#define SMEM_DYN (32 * 257 * 16)

__device__ __forceinline__ float sigf(float x) { return 1.f / (1.f + expf(-x)); }

// ---------------- init ----------------
__global__ void init_kernel(const int* __restrict__ pos, const int* __restrict__ word,
                            const float* __restrict__ pos_emb, const float* __restrict__ word_emb,
                            float* __restrict__ S)
{
    int i = blockIdx.x * blockDim.x + threadIdx.x;
    int stride = gridDim.x * blockDim.x;
    float* pemb = S + OFF_PEMB;
    float* wemb = S + OFF_WEMB;
    for (int idx = i; idx < TT*BATCH*PE; idx += stride) {
        int tb = idx / PE, e = idx - tb*PE;
        pemb[idx] = pos_emb[pos[tb]*PE + e];
    }
    for (int idx = i; idx < TT*BATCH*WE; idx += stride) {
        int tb = idx / WE, e = idx - tb*WE;
        wemb[idx] = word_emb[word[tb]*WE + e];
    }
    for (int idx = i; idx < 3*SZ_PH; idx += stride) S[OFF_PH0 + idx] = 0.f;
    for (int idx = i; idx < 6*SZ_WH; idx += stride) S[OFF_WH0A + idx] = 0.f;
}

// ---------------- fp32 -> bf16 conversion (vectorized) ----------------
__global__ void conv_bf16(const float* __restrict__ src, __nv_bfloat16* __restrict__ dst,
                          int n4)
{
    int i = blockIdx.x * blockDim.x + threadIdx.x;
    int st = gridDim.x * blockDim.x;
    const float4* s4 = (const float4*)src;
    for (; i < n4; i += st) {
        float4 v = s4[i];
        __nv_bfloat162 lo = __floats2bfloat162_rn(v.x, v.y);
        __nv_bfloat162 hi = __floats2bfloat162_rn(v.z, v.w);
        *(__nv_bfloat162*)(dst + (size_t)i*4)     = lo;
        *(__nv_bfloat162*)(dst + (size_t)i*4 + 2) = hi;
    }
}

// ---------------- grid barrier ----------------
__device__ __forceinline__ void grid_bar()
{
    __threadfence();
    __syncthreads();
    if (threadIdx.x == 0) {
        volatile unsigned* gen = &g_bar_gen;
        unsigned g = *gen;
        unsigned a = atomicAdd(&g_bar_cnt, 1u);
        if (a == GRID - 1u) {
            g_bar_cnt = 0u;
            __threadfence();
            atomicAdd(&g_bar_gen, 1u);
        } else {
            while (*gen == g) __nanosleep(32);
        }
    }
    __syncthreads();
    __threadfence();
}

// ---------------- A staging into padded smem ----------------
__device__ __forceinline__ void stage_if(const float* A, int K, float* sAdyn,
                                         const float* volatile* s_staged)
{
    if (*s_staged != A) {
        __syncthreads();
        int K4 = K >> 2;
        const float4* A4 = (const float4*)A;
        float4* S4 = (float4*)sAdyn;
        for (int i = threadIdx.x; i < 32*K4; i += TPB) {
            int row = i / K4, kq = i - row*K4;
            S4[row*(K4+1) + kq] = A4[row*K4 + kq];
        }
        if (threadIdx.x == 0) *s_staged = A;
        __syncthreads();
    }
}

// ---------------- per-warp 4-col K-slice accumulate (software-pipelined) ----------------
__device__ __forceinline__ float fma4f(float acc, float4 a, float4 b)
{
    return fmaf(a.x, b.x, fmaf(a.y, b.y, fmaf(a.z, b.z, fmaf(a.w, b.w, acc))));
}

__device__ __forceinline__ void accum4(const float* __restrict__ W, int ldw, int wcol, int K,
                                       const int* n, int s, float* acc,
                                       const float* __restrict__ sAdyn)
{
    int lane = threadIdx.x & 31;
    int K4 = K >> 2;
    int Q  = K4 >> 2;                       // float4 groups per slice (>=16, even)
    const float4* a4 = (const float4*)sAdyn + lane*(K4+1);
    const float4* W0 = (const float4*)(W + (size_t)n[0]*ldw + wcol);
    const float4* W1 = (const float4*)(W + (size_t)n[1]*ldw + wcol);
    const float4* W2 = (const float4*)(W + (size_t)n[2]*ldw + wcol);
    const float4* W3 = (const float4*)(W + (size_t)n[3]*ldw + wcol);
    int q0 = s*Q, q1 = q0 + Q;
    float acc2[4] = {0.f, 0.f, 0.f, 0.f};
    #pragma unroll 4
    for (int q = q0; q < q1; q += 2) {
        // batch all 8 W loads (warp-uniform L2 hits) before any FMA -> high MLP
        float4 u0 = __ldg(W0+q),   u1 = __ldg(W1+q),   u2 = __ldg(W2+q),   u3 = __ldg(W3+q);
        float4 v0 = __ldg(W0+q+1), v1 = __ldg(W1+q+1), v2 = __ldg(W2+q+1), v3 = __ldg(W3+q+1);
        float4 a0 = a4[q], a1 = a4[q+1];
        acc[0]  = fma4f(acc[0],  a0, u0);
        acc[1]  = fma4f(acc[1],  a0, u1);
        acc[2]  = fma4f(acc[2],  a0, u2);
        acc[3]  = fma4f(acc[3],  a0, u3);
        acc2[0] = fma4f(acc2[0], a1, v0);
        acc2[1] = fma4f(acc2[1], a1, v1);
        acc2[2] = fma4f(acc2[2], a1, v2);
        acc2[3] = fma4f(acc2[3], a1, v3);
    }
    #pragma unroll
    for (int c = 0; c < 4; c++) acc[c] += acc2[c];
}

// ---------------- persistent sequential-phase kernel ----------------
__global__ __launch_bounds__(TPB, 1) void persist_kernel(
    const float* __restrict__ w2p_W, const float* __restrict__ w2p_b,
    const float* __restrict__ p2w_W, const float* __restrict__ p2w_b,
    const float* __restrict__ p_Wih0, const float* __restrict__ p_Whh0,
    const float* __restrict__ w_Wih0, const float* __restrict__ w_Whh0,
    const float* __restrict__ w_Wih1, const float* __restrict__ w_Whh1,
    const float* __restrict__ w_bih1, const float* __restrict__ w_bhh1,
    float* __restrict__ S)
{
    extern __shared__ float sA[];
    __shared__ float red[4][16][33];
    __shared__ const float* volatile s_staged;

    float* gpseq = S + OFF_GPSEQ;
    float* gwseq = S + OFF_GWSEQ;
    float* phb[2]  = { S + OFF_PH0,  S + OFF_PH1 };
    float* pc    = S + OFF_PC;
    float* wh0b[2] = { S + OFF_WH0A, S + OFF_WH0B };
    float* wc0   = S + OFF_WC0;
    float* wh1b[2] = { S + OFF_WH1A, S + OFF_WH1B };
    float* wc1   = S + OFF_WC1;
    float* lastw = S + OFF_LASTW;
    float* lastp = S + OFF_LASTP;
    float* wg0h  = S + OFF_WG0H;
    float* wg1h  = S + OFF_WG1H;
    float* phseq = S + OFF_PHSEQ;
    float* whseq = S + OFF_WHSEQ;

    int lane = threadIdx.x & 31;
    int wrp  = threadIdx.x >> 5;
    int s    = wrp & 3;
    int cg   = wrp >> 2;

    if (threadIdx.x == 0) s_staged = nullptr;
    __syncthreads();

    int pp = 0, pw0 = 0, pw1 = 0;

    for (int t = 0; t < TT; t++) {
        const float* wh1c = wh1b[pw1];
        const float* wh0c = wh0b[pw0];

        // ===== S1: lastw (tanh), wg1h, wg0h =====
        for (int gid = blockIdx.x; gid < 576; gid += GRID) {
            const float* A; const float* W; float* dst; const float* bias;
            int n0, Ntot, epi;
            if (gid < 64)       { A=wh1c; W=w2p_W;  dst=lastw; bias=w2p_b; n0=gid*16;        Ntot=WH;   epi=1; }
            else if (gid < 320) { A=wh1c; W=w_Whh1; dst=wg1h;  bias=0;     n0=(gid-64)*16;   Ntot=4*WH; epi=0; }
            else                { A=wh0c; W=w_Whh0; dst=wg0h;  bias=0;     n0=(gid-320)*16;  Ntot=4*WH; epi=0; }
            stage_if(A, WH, sA, &s_staged);
            int n[4]; float acc[4] = {0,0,0,0};
            #pragma unroll
            for (int c = 0; c < 4; c++) n[c] = n0 + cg*4 + c;
            accum4(W, WH, 0, WH, n, s, acc, sA);
            #pragma unroll
            for (int c = 0; c < 4; c++) red[s][cg*4+c][lane] = acc[c];
            __syncthreads();
            {
                float v = red[0][wrp][lane] + red[1][wrp][lane]
                        + red[2][wrp][lane] + red[3][wrp][lane];
                int nn = n0 + wrp;
                if (epi) dst[lane*Ntot + nn] = tanhf(v + bias[nn]);
                else     dst[lane*Ntot + nn] = v;
            }
            __syncthreads();
        }
        grid_bar();
        if (threadIdx.x == 0) s_staged = nullptr;
        __syncthreads();

        // ===== S2: POS gates + cell =====
        const float* phc = phb[pp];
        float* phn = phb[pp^1];
        for (int gid = blockIdx.x; gid < 64; gid += GRID) {
            int j0 = gid*4;
            int n[4]; float acc[4] = {0,0,0,0};
            #pragma unroll
            for (int c = 0; c < 4; c++) n[c] = cg*PH + j0 + c;
            stage_if(lastw, WH, sA, &s_staged);
            accum4(p_Wih0, PE+WH, PE, WH, n, s, acc, sA);
            stage_if(phc, PH, sA, &s_staged);
            accum4(p_Whh0, PH, 0, PH, n, s, acc, sA);
            #pragma unroll
            for (int c = 0; c < 4; c++) red[s][cg*4+c][lane] = acc[c];
            __syncthreads();
            if (threadIdx.x < 128) {
                int jl = wrp, b = lane;
                int j = j0 + jl;
                const float* pre = gpseq + ((size_t)t*BATCH + b)*4*PH;
                float g[4];
                #pragma unroll
                for (int gate = 0; gate < 4; gate++) {
                    int cc = gate*4 + jl;
                    g[gate] = red[0][cc][b] + red[1][cc][b] + red[2][cc][b] + red[3][cc][b]
                            + pre[gate*PH + j];
                }
                float si = sigf(g[0]), sf = sigf(g[1]), so = sigf(g[3]);
                int idx = b*PH + j;
                float cn = sf * pc[idx] + si * tanhf(g[2]);
                float hn = so * tanhf(cn);
                pc[idx] = cn; phn[idx] = hn;
                phseq[((size_t)t*BATCH + b)*PH + j] = hn;
            }
            __syncthreads();
        }
        grid_bar();
        if (threadIdx.x == 0) s_staged = nullptr;
        __syncthreads();

        // ===== S3: lastp = tanh(phn @ p2w^T + b) =====
        for (int gid = blockIdx.x; gid < 16; gid += GRID) {
            int n0 = gid*16;
            int n[4]; float acc[4] = {0,0,0,0};
            #pragma unroll
            for (int c = 0; c < 4; c++) n[c] = n0 + cg*4 + c;
            stage_if(phn, PH, sA, &s_staged);
            accum4(p2w_W, PH, 0, PH, n, s, acc, sA);
            #pragma unroll
            for (int c = 0; c < 4; c++) red[s][cg*4+c][lane] = acc[c];
            __syncthreads();
            {
                float v = red[0][wrp][lane] + red[1][wrp][lane]
                        + red[2][wrp][lane] + red[3][wrp][lane];
                int nn = n0 + wrp;
                lastp[lane*PH + nn] = tanhf(v + p2w_b[nn]);
            }
            __syncthreads();
        }
        grid_bar();
        if (threadIdx.x == 0) s_staged = nullptr;
        __syncthreads();

        // ===== S4: WORD L0 gates + cell =====
        float* wh0n = wh0b[pw0^1];
        for (int gid = blockIdx.x; gid < 256; gid += GRID) {
            int j0 = gid*4;
            int n[4]; float acc[4] = {0,0,0,0};
            #pragma unroll
            for (int c = 0; c < 4; c++) n[c] = cg*WH + j0 + c;
            stage_if(lastp, PH, sA, &s_staged);
            accum4(w_Wih0, WE+PH, WE, PH, n, s, acc, sA);
            #pragma unroll
            for (int c = 0; c < 4; c++) red[s][cg*4+c][lane] = acc[c];
            __syncthreads();
            if (threadIdx.x < 128) {
                int jl = wrp, b = lane;
                int j = j0 + jl;
                const float* pre = gwseq + ((size_t)t*BATCH + b)*4*WH;
                const float* hid = wg0h + (size_t)b*4*WH;
                float g[4];
                #pragma unroll
                for (int gate = 0; gate < 4; gate++) {
                    int cc = gate*4 + jl;
                    int nn = gate*WH + j;
                    g[gate] = red[0][cc][b] + red[1][cc][b] + red[2][cc][b] + red[3][cc][b]
                            + pre[nn] + hid[nn];
                }
                float si = sigf(g[0]), sf = sigf(g[1]), so = sigf(g[3]);
                int idx = b*WH + j;
                float cn = sf * wc0[idx] + si * tanhf(g[2]);
                float hn = so * tanhf(cn);
                wc0[idx] = cn; wh0n[idx] = hn;
            }
            __syncthreads();
        }
        grid_bar();
        if (threadIdx.x == 0) s_staged = nullptr;
        __syncthreads();
        pw0 ^= 1;

        // ===== S5: WORD L1 gates + cell =====
        float* wh1n = wh1b[pw1^1];
        const float* wh0new = wh0b[pw0];
        for (int gid = blockIdx.x; gid < 256; gid += GRID) {
            int j0 = gid*4;
            int n[4]; float acc[4] = {0,0,0,0};
            #pragma unroll
            for (int c = 0; c < 4; c++) n[c] = cg*WH + j0 + c;
            stage_if(wh0new, WH, sA, &s_staged);
            accum4(w_Wih1, WH, 0, WH, n, s, acc, sA);
            #pragma unroll
            for (int c = 0; c < 4; c++) red[s][cg*4+c][lane] = acc[c];
            __syncthreads();
            if (threadIdx.x < 128) {
                int jl = wrp, b = lane;
                int j = j0 + jl;
                const float* hid = wg1h + (size_t)b*4*WH;
                float g[4];
                #pragma unroll
                for (int gate = 0; gate < 4; gate++) {
                    int cc = gate*4 + jl;
                    int nn = gate*WH + j;
                    g[gate] = red[0][cc][b] + red[1][cc][b] + red[2][cc][b] + red[3][cc][b]
                            + hid[nn] + w_bih1[nn] + w_bhh1[nn];
                }
                float si = sigf(g[0]), sf = sigf(g[1]), so = sigf(g[3]);
                int idx = b*WH + j;
                float cn = sf * wc1[idx] + si * tanhf(g[2]);
                float hn = so * tanhf(cn);
                wc1[idx] = cn; wh1n[idx] = hn;
                whseq[((size_t)t*BATCH + b)*WH + j] = hn;
            }
            __syncthreads();
        }
        grid_bar();
        if (threadIdx.x == 0) s_staged = nullptr;
        __syncthreads();
        pw1 ^= 1;
        pp  ^= 1;
    }
}

// ---------------- big GEMM (fp32): C[M,N] = A[M,K] @ W[N, wcol:wcol+K]^T + b1 (+b2) ----------------
__global__ __launch_bounds__(256) void big_gemm(const float* __restrict__ A, int lda,
                                                const float* __restrict__ W, int ldw, int wcol,
                                                const float* __restrict__ bias1,
                                                const float* __restrict__ bias2,
                                                float* __restrict__ C, long ldc, int K)
{
    __shared__ float sAa[16][132];
    __shared__ float sW[16][68];
    int tx = threadIdx.x & 15, ty = threadIdx.x >> 4;
    int bm = blockIdx.y * 128, bn = blockIdx.x * 64;
    float acc[8][4];
    #pragma unroll
    for (int i = 0; i < 8; i++)
        #pragma unroll
        for (int j = 0; j < 4; j++) acc[i][j] = 0.f;

    for (int kt = 0; kt < K; kt += 16) {
        __syncthreads();
        #pragma unroll
        for (int i = 0; i < 2; i++) {
            int f = threadIdx.x + i*256;
            int row = f >> 2, kq = (f & 3) * 4;
            float4 v = *reinterpret_cast<const float4*>(A + (long)(bm+row)*lda + kt + kq);
            sAa[kq][row] = v.x; sAa[kq+1][row] = v.y; sAa[kq+2][row] = v.z; sAa[kq+3][row] = v.w;
        }
        {
            int f = threadIdx.x;
            int row = f >> 2, kq = (f & 3) * 4;
            float4 v = *reinterpret_cast<const float4*>(W + (long)(bn+row)*ldw + wcol + kt + kq);
            sW[kq][row] = v.x; sW[kq+1][row] = v.y; sW[kq+2][row] = v.z; sW[kq+3][row] = v.w;
        }
        __syncthreads();
        #pragma unroll
        for (int k = 0; k < 16; k++) {
            float4 a0 = *reinterpret_cast<float4*>(&sAa[k][ty*8]);
            float4 a1 = *reinterpret_cast<float4*>(&sAa[k][ty*8+4]);
            float4 w  = *reinterpret_cast<float4*>(&sW[k][tx*4]);
            float am[8] = {a0.x,a0.y,a0.z,a0.w,a1.x,a1.y,a1.z,a1.w};
            float wn[4] = {w.x,w.y,w.z,w.w};
            #pragma unroll
            for (int i = 0; i < 8; i++)
                #pragma unroll
                for (int j = 0; j < 4; j++)
                    acc[i][j] = fmaf(am[i], wn[j], acc[i][j]);
        }
    }

    float bv[4];
    #pragma unroll
    for (int j = 0; j < 4; j++) {
        int nn = bn + tx*4 + j;
        bv[j] = (bias1 ? bias1[nn] : 0.f) + (bias2 ? bias2[nn] : 0.f);
    }
    #pragma unroll
    for (int i = 0; i < 8; i++) {
        int m = bm + ty*8 + i;
        float4 o;
        o.x = acc[i][0] + bv[0]; o.y = acc[i][1] + bv[1];
        o.z = acc[i][2] + bv[2]; o.w = acc[i][3] + bv[3];
        *reinterpret_cast<float4*>(C + (long)m*ldc + bn + tx*4) = o;
    }
}

// ---------------- tensor-core vocab GEMM ----------------
__device__ __forceinline__ void mma16816(float* c, const unsigned* a, const unsigned* b)
{
    asm volatile("mma.sync.aligned.m16n8k16.row.col.f32.bf16.bf16.f32 "
        "{%0,%1,%2,%3}, {%4,%5,%6,%7}, {%8,%9}, {%0,%1,%2,%3};"
        : "+f"(c[0]), "+f"(c[1]), "+f"(c[2]), "+f"(c[3])
        : "r"(a[0]), "r"(a[1]), "r"(a[2]), "r"(a[3]), "r"(b[0]), "r"(b[1]));
}

__device__ __forceinline__ void ldsm4(unsigned* r, const void* p)
{
    unsigned ad = (unsigned)__cvta_generic_to_shared(p);
    asm volatile("ldmatrix.sync.aligned.m8n8.x4.shared.b16 {%0,%1,%2,%3}, [%4];"
        : "=r"(r[0]), "=r"(r[1]), "=r"(r[2]), "=r"(r[3]) : "r"(ad));
}

__global__ __launch_bounds__(256) void vocab_mma(const __nv_bfloat16* __restrict__ Abf,
                                                 const __nv_bfloat16* __restrict__ Bbf,
                                                 const float* __restrict__ bias,
                                                 float* __restrict__ C)
{
    __shared__ __nv_bfloat16 sAm[128][40];
    __shared__ __nv_bfloat16 sBm[128][40];
    int tid = threadIdx.x;
    int lane = tid & 31, wid = tid >> 5;
    int wm = wid >> 2, wn = wid & 3;
    int bm = blockIdx.y * 128, bn = blockIdx.x * 128;

    float acc[4][4][4] = {};

    for (int kt = 0; kt < WE; kt += 32) {
        __syncthreads();
        #pragma unroll
        for (int c = 0; c < 2; c++) {
            int ch = tid + c*256;
            int row = ch >> 2, seg = (ch & 3) * 8;
            *(uint4*)&sAm[row][seg] = *(const uint4*)&Abf[(size_t)(bm+row)*WE + kt + seg];
            *(uint4*)&sBm[row][seg] = *(const uint4*)&Bbf[(size_t)(bn+row)*WE + kt + seg];
        }
        __syncthreads();
        #pragma unroll
        for (int k16 = 0; k16 < 2; k16++) {
            unsigned afrag[4][4], bfrag[4][2];
            #pragma unroll
            for (int mf = 0; mf < 4; mf++) {
                int row = wm*64 + mf*16 + (lane & 15);
                int col = k16*16 + (lane >> 4) * 8;
                ldsm4(afrag[mf], &sAm[row][col]);
            }
            #pragma unroll
            for (int np = 0; np < 2; np++) {
                int row = wn*32 + np*16 + (lane & 7) + ((lane >> 4) << 3);
                int col = k16*16 + (((lane >> 3) & 1) << 3);
                unsigned r[4];
                ldsm4(r, &sBm[row][col]);
                bfrag[np*2][0]   = r[0]; bfrag[np*2][1]   = r[1];
                bfrag[np*2+1][0] = r[2]; bfrag[np*2+1][1] = r[3];
            }
            #pragma unroll
            for (int mf = 0; mf < 4; mf++)
                #pragma unroll
                for (int nf = 0; nf < 4; nf++)
                    mma16816(acc[mf][nf], afrag[mf], bfrag[nf]);
        }
    }

    int tg = lane >> 2;
    int tc = (lane & 3) * 2;
    #pragma unroll
    for (int nf = 0; nf < 4; nf++) {
        int n = bn + wn*32 + nf*8 + tc;
        float b0 = bias[n], b1 = bias[n+1];
        #pragma unroll
        for (int mf = 0; mf < 4; mf++) {
            int m0 = bm + wm*64 + mf*16 + tg;
            float2 v0 = { acc[mf][nf][0] + b0, acc[mf][nf][1] + b1 };
            float2 v1 = { acc[mf][nf][2] + b0, acc[mf][nf][3] + b1 };
            *(float2*)&C[(size_t)m0*WV + n]     = v0;
            *(float2*)&C[(size_t)(m0+8)*WV + n] = v1;
        }
    }
}

// ---------------- pos projection + log_softmax (48-way) ----------------
__global__ void pos_out_kernel(const float* __restrict__ phseq,
                               const float* __restrict__ proj_W,
                               const float* __restrict__ proj_b,
                               float* __restrict__ out)
{
    int row = blockIdx.x;
    const float* h = phseq + row * PH;
    __shared__ float sh[PH];
    __shared__ float logits[PV];
    __shared__ float lse;
    for (int i = threadIdx.x; i < PH; i += 64) sh[i] = h[i];
    __syncthreads();
    if (threadIdx.x < PV) {
        float s = proj_b[threadIdx.x];
        const float* wr = proj_W + threadIdx.x * PH;
        #pragma unroll 4
        for (int k = 0; k < PH; k++) s += sh[k] * wr[k];
        logits[threadIdx.x] = s;
    }
    __syncthreads();
    if (threadIdx.x == 0) {
        float m = -1e30f;
        for (int i = 0; i < PV; i++) m = fmaxf(m, logits[i]);
        float ssum = 0.f;
        for (int i = 0; i < PV; i++) ssum += expf(logits[i] - m);
        lse = m + logf(ssum);
    }
    __syncthreads();
    if (threadIdx.x < PV) out[row * PV + threadIdx.x] = logits[threadIdx.x] - lse;
}

// ---------------- in-place log_softmax over rows of WV ----------------
__global__ void word_lsm(float* __restrict__ out)
{
    int row = blockIdx.x;
    float* r = out + (long)row * WV;
    float m = -1e30f, s = 0.f;
    for (int i = threadIdx.x; i < WV; i += blockDim.x) {
        float v = r[i];
        if (v > m) { s = s * expf(m - v) + 1.f; m = v; }
        else       { s += expf(v - m); }
    }
    __shared__ float sm[256], ss[256];
    sm[threadIdx.x] = m; ss[threadIdx.x] = s;
    __syncthreads();
    for (int off = 128; off > 0; off >>= 1) {
        if (threadIdx.x < off) {
            float m1 = sm[threadIdx.x], s1 = ss[threadIdx.x];
            float m2 = sm[threadIdx.x + off], s2 = ss[threadIdx.x + off];
            float mm = fmaxf(m1, m2);
            sm[threadIdx.x] = mm;
            ss[threadIdx.x] = s1 * expf(m1 - mm) + s2 * expf(m2 - mm);
        }
        __syncthreads();
    }
    float lse = sm[0] + logf(ss[0]);
    for (int i = threadIdx.x; i < WV; i += blockDim.x) r[i] -= lse;
}

// ---------------- host orchestration ----------------
extern "C" void kernel_launch(void* const* d_in, const int* in_sizes, int n_in,
                              void* d_out, int out_size)
{
    (void)in_sizes; (void)n_in; (void)out_size;
    const int*   pos          = (const int*)  d_in[0];
    const int*   word         = (const int*)  d_in[1];
    const float* pos_emb_W    = (const float*)d_in[2];
    const float* word_emb_W   = (const float*)d_in[3];
    const float* w2p_W        = (const float*)d_in[4];
    const float* w2p_b        = (const float*)d_in[5];
    const float* p2w_W        = (const float*)d_in[6];
    const float* p2w_b        = (const float*)d_in[7];
    const float* p_Wih0       = (const float*)d_in[8];
    const float* p_Whh0       = (const float*)d_in[9];
    const float* p_bih0       = (const float*)d_in[10];
    const float* p_bhh0       = (const float*)d_in[11];
    const float* w_Wih0       = (const float*)d_in[12];
    const float* w_Whh0       = (const float*)d_in[13];
    const float* w_bih0       = (const float*)d_in[14];
    const float* w_bhh0       = (const float*)d_in[15];
    const float* w_Wih1       = (const float*)d_in[16];
    const float* w_Whh1       = (const float*)d_in[17];
    const float* w_bih1       = (const float*)d_in[18];
    const float* w_bhh1       = (const float*)d_in[19];
    const float* pos_proj_W   = (const float*)d_in[20];
    const float* pos_proj_b   = (const float*)d_in[21];
    const float* word_proj1_W = (const float*)d_in[22];
    const float* word_proj1_b = (const float*)d_in[23];
    const float* word_proj2_b = (const float*)d_in[24];
    float* out = (float*)d_out;

    float* S = nullptr;
    cudaGetSymbolAddress((void**)&S, g_scratch);
    __nv_bfloat16* wemb_bf = nullptr;
    cudaGetSymbolAddress((void**)&wemb_bf, g_wemb_bf);
    __nv_bfloat16* he_bf = nullptr;
    cudaGetSymbolAddress((void**)&he_bf, g_he_bf);

    float* pemb  = S + OFF_PEMB;
    float* wemb  = S + OFF_WEMB;
    float* gpseq = S + OFF_GPSEQ;
    float* gwseq = S + OFF_GWSEQ;
    float* phseq = S + OFF_PHSEQ;
    float* whseq = S + OFF_WHSEQ;
    float* he    = S + OFF_HE;

    static bool attr_set = false;
    if (!attr_set) {
        cudaFuncSetAttribute(persist_kernel, cudaFuncAttributeMaxDynamicSharedMemorySize, SMEM_DYN);
        attr_set = true;
    }

    init_kernel<<<256, 256>>>(pos, word, pos_emb_W, word_emb_W, S);

    conv_bf16<<<2048, 256>>>(word_emb_W, wemb_bf, (int)((size_t)WV*WE/4));

    big_gemm<<<dim3(4*PH/64, TT*BATCH/128), 256>>>(pemb, PE, p_Wih0, PE+WH, 0,
                                                   p_bih0, p_bhh0, gpseq, 4*PH, PE);
    big_gemm<<<dim3(4*WH/64, TT*BATCH/128), 256>>>(wemb, WE, w_Wih0, WE+PH, 0,
                                                   w_bih0, w_bhh0, gwseq, 4*WH, WE);

    persist_kernel<<<GRID, TPB, SMEM_DYN>>>(
        w2p_W, w2p_b, p2w_W, p2w_b,
        p_Wih0, p_Whh0, w_Wih0, w_Whh0,
        w_Wih1, w_Whh1, w_bih1, w_bhh1, S);

    pos_out_kernel<<<TT*BATCH, 64>>>(phseq, pos_proj_W, pos_proj_b, out);

    big_gemm<<<dim3(WE/64, TT*BATCH/128), 256>>>(whseq, WH, word_proj1_W, WH, 0,
                                                 word_proj1_b, nullptr, he, WE, WH);
    conv_bf16<<<1024, 256>>>(he, he_bf, (int)((size_t)TT*BATCH*WE/4));

    float* wout = out + (long)TT*BATCH*PV;
    vocab_mma<<<dim3(WV/128, TT*BATCH/128), 256>>>(he_bf, wemb_bf, word_proj2_b, wout);
    word_lsm<<<TT*BATCH, 256>>>(wout);
}